// round 1
// baseline (speedup 1.0000x reference)
#include <cuda_runtime.h>
#include <cstdint>

#define T_TOK 4096
#define E_DIM 4096
#define B_SZ  4
#define S_LEN 1024
#define H_NUM 32
#define D_HEAD 128
#define BS_BLK 16
#define NB_BLK 64

// Scratch (allocation-free rule: __device__ globals)
__device__ float g_qkv[3ULL * T_TOK * E_DIM];     // q | k | v, each [T, E]
__device__ float g_attn[(size_t)T_TOK * E_DIM];   // attention output [T, E]

// ---------------------------------------------------------------------------
// Tiled SGEMM: C[z] = A @ B[z], all row-major, M=N=K=4096-ish (multiples of 128/8)
// Block 256 threads, tile 128x128, K-tile 8, 8x8 per-thread micro-tile.
// ---------------------------------------------------------------------------
__global__ __launch_bounds__(256, 2)
void sgemm_kernel(const float* __restrict__ A, const float* __restrict__ Bmat,
                  float* __restrict__ C, int M, int N, int K,
                  long long strideB, long long strideC)
{
    const float* B = Bmat + (long long)blockIdx.z * strideB;
    float*      Cz = C    + (long long)blockIdx.z * strideC;

    __shared__ float As[8][128];
    __shared__ float Bs[8][128];

    int tid = threadIdx.x;
    int m0 = blockIdx.y * 128;
    int n0 = blockIdx.x * 128;
    int tx = tid & 15, ty = tid >> 4;

    float acc[8][8];
    #pragma unroll
    for (int i = 0; i < 8; i++)
        #pragma unroll
        for (int j = 0; j < 8; j++) acc[i][j] = 0.f;

    int aRow = tid >> 1;           // 0..127
    int aCol = (tid & 1) * 4;      // 0 or 4
    int bRow = tid >> 5;           // 0..7
    int bCol = (tid & 31) * 4;     // 0..124

    for (int k0 = 0; k0 < K; k0 += 8) {
        float4 av = *(const float4*)&A[(long long)(m0 + aRow) * K + k0 + aCol];
        As[aCol + 0][aRow] = av.x;
        As[aCol + 1][aRow] = av.y;
        As[aCol + 2][aRow] = av.z;
        As[aCol + 3][aRow] = av.w;
        float4 bv = *(const float4*)&B[(long long)(k0 + bRow) * N + n0 + bCol];
        *(float4*)&Bs[bRow][bCol] = bv;
        __syncthreads();

        #pragma unroll
        for (int kk = 0; kk < 8; kk++) {
            float a[8], b[8];
            #pragma unroll
            for (int i = 0; i < 8; i++) a[i] = As[kk][ty * 8 + i];
            #pragma unroll
            for (int j = 0; j < 8; j++) b[j] = Bs[kk][tx * 8 + j];
            #pragma unroll
            for (int i = 0; i < 8; i++)
                #pragma unroll
                for (int j = 0; j < 8; j++)
                    acc[i][j] += a[i] * b[j];
        }
        __syncthreads();
    }

    #pragma unroll
    for (int i = 0; i < 8; i++) {
        long long crow = (long long)(m0 + ty * 8 + i) * N + n0 + tx * 8;
        *(float4*)&Cz[crow]     = make_float4(acc[i][0], acc[i][1], acc[i][2], acc[i][3]);
        *(float4*)&Cz[crow + 4] = make_float4(acc[i][4], acc[i][5], acc[i][6], acc[i][7]);
    }
}

// ---------------------------------------------------------------------------
// RoPE (in-place on q and k slices of g_qkv)
// ---------------------------------------------------------------------------
__global__ void rope_kernel(float* __restrict__ qkv,
                            const float* __restrict__ cosv,
                            const float* __restrict__ sinv)
{
    long long idx = (long long)blockIdx.x * blockDim.x + threadIdx.x;
    // 2 (q,k) * T * H * 64 pairs
    if (idx >= 2LL * T_TOK * H_NUM * 64) return;
    int j = idx & 63;
    int h = (idx >> 6) & (H_NUM - 1);
    long long t = (idx >> 11) & (T_TOK - 1);
    int which = (int)(idx >> (6 + 5 + 12));   // 0 = q, 1 = k
    float* base = qkv + (long long)which * T_TOK * E_DIM + t * E_DIM + h * D_HEAD;
    float c = cosv[t * 64 + j];
    float s = sinv[t * 64 + j];
    float x1 = base[j];
    float x2 = base[j + 64];
    base[j]      = x1 * c - x2 * s;
    base[j + 64] = x2 * c + x1 * s;
}

// ---------------------------------------------------------------------------
// KV cache scatter: k,v (post-RoPE k) -> cache layout [blk, H, BS, D]
// ---------------------------------------------------------------------------
__global__ void cache_write_kernel(const float* __restrict__ qkv,
                                   const int* __restrict__ block_tables,
                                   float* __restrict__ out_k,
                                   float* __restrict__ out_v)
{
    long long idx = (long long)blockIdx.x * blockDim.x + threadIdx.x;
    if (idx >= (long long)B_SZ * NB_BLK * H_NUM * BS_BLK * D_HEAD) return;
    int d  = idx & 127;
    int bs = (idx >> 7) & (BS_BLK - 1);
    int h  = (idx >> 11) & (H_NUM - 1);
    long long nbb = idx >> 16;         // b*NB + nb
    int b  = (int)(nbb >> 6);
    int nb = (int)(nbb & 63);
    int blk = block_tables[b * NB_BLK + nb];
    long long t = (long long)b * S_LEN + nb * BS_BLK + bs;
    long long src = t * E_DIM + h * D_HEAD + d;
    long long dst = (((long long)blk * H_NUM + h) * BS_BLK + bs) * D_HEAD + d;
    out_k[dst] = qkv[(long long)T_TOK * E_DIM + src];
    out_v[dst] = qkv[2LL * T_TOK * E_DIM + src];
}

// ---------------------------------------------------------------------------
// Flash attention, fp32, causal. Q-tile 64, K-tile 64, 256 threads.
// Micro-tile mapping: rows qi = ty+16i, cols ki = tx+16j (conflict-free at
// stride 129); PV output cols d = tx*8+jj (float4 at stride 132).
// ---------------------------------------------------------------------------
#define QS_STRIDE 129
#define KS_STRIDE 129
#define VS_STRIDE 132
#define PS_STRIDE 65

__global__ __launch_bounds__(256, 1)
void attn_kernel(const float* __restrict__ qkv, float* __restrict__ attn_out)
{
    extern __shared__ float sm[];
    float* Qs = sm;                          // 64*129
    float* Ks = Qs + 64 * QS_STRIDE;         // 64*129
    float* Vs = Ks + 64 * KS_STRIDE;         // 64*132
    float* Ps = Vs + 64 * VS_STRIDE;         // 64*65
    float* alpha_sh = Ps + 64 * PS_STRIDE;   // 64
    float* l_sh = alpha_sh + 64;             // 64

    int tid = threadIdx.x;
    int tx = tid & 15, ty = tid >> 4;
    int qt = blockIdx.x, h = blockIdx.y, b = blockIdx.z;
    int q0 = qt * 64;

    const long long TE = (long long)T_TOK * E_DIM;
    const float* qbase = qkv;
    const float* kbase = qkv + TE;
    const float* vbase = qkv + 2 * TE;
    const float scale = 0.08838834764831845f;  // 1/sqrt(128)

    // Load Q tile
    for (int c = tid; c < 64 * 32; c += 256) {
        int row = c >> 5;
        int c4 = (c & 31) * 4;
        float4 v = *(const float4*)&qbase[((long long)(b * S_LEN + q0 + row)) * E_DIM + h * D_HEAD + c4];
        Qs[row * QS_STRIDE + c4]     = v.x;
        Qs[row * QS_STRIDE + c4 + 1] = v.y;
        Qs[row * QS_STRIDE + c4 + 2] = v.z;
        Qs[row * QS_STRIDE + c4 + 3] = v.w;
    }

    float m_r = -1e30f, l_r = 0.f;   // softmax state for row tid/4
    float o[4][8];
    #pragma unroll
    for (int i = 0; i < 4; i++)
        #pragma unroll
        for (int j = 0; j < 8; j++) o[i][j] = 0.f;

    int nkt = qt + 1;
    for (int kt = 0; kt < nkt; kt++) {
        int k0 = kt * 64;
        __syncthreads();   // Q ready (iter 0) / prior PV done
        for (int c = tid; c < 64 * 32; c += 256) {
            int row = c >> 5;
            int c4 = (c & 31) * 4;
            long long goff = ((long long)(b * S_LEN + k0 + row)) * E_DIM + h * D_HEAD + c4;
            float4 kv = *(const float4*)&kbase[goff];
            Ks[row * KS_STRIDE + c4]     = kv.x;
            Ks[row * KS_STRIDE + c4 + 1] = kv.y;
            Ks[row * KS_STRIDE + c4 + 2] = kv.z;
            Ks[row * KS_STRIDE + c4 + 3] = kv.w;
            float4 vv = *(const float4*)&vbase[goff];
            *(float4*)&Vs[row * VS_STRIDE + c4] = vv;
        }
        __syncthreads();

        // --- scores: s[i][j] = Q[ty+16i] . K[tx+16j] ---
        float s[4][4];
        #pragma unroll
        for (int i = 0; i < 4; i++)
            #pragma unroll
            for (int j = 0; j < 4; j++) s[i][j] = 0.f;
        const float* qr0 = &Qs[(ty +  0) * QS_STRIDE];
        const float* qr1 = &Qs[(ty + 16) * QS_STRIDE];
        const float* qr2 = &Qs[(ty + 32) * QS_STRIDE];
        const float* qr3 = &Qs[(ty + 48) * QS_STRIDE];
        const float* kr0 = &Ks[(tx +  0) * KS_STRIDE];
        const float* kr1 = &Ks[(tx + 16) * KS_STRIDE];
        const float* kr2 = &Ks[(tx + 32) * KS_STRIDE];
        const float* kr3 = &Ks[(tx + 48) * KS_STRIDE];
        #pragma unroll 4
        for (int d = 0; d < 128; d++) {
            float a0 = qr0[d], a1 = qr1[d], a2 = qr2[d], a3 = qr3[d];
            float b0 = kr0[d], b1 = kr1[d], b2 = kr2[d], b3 = kr3[d];
            s[0][0] += a0 * b0; s[0][1] += a0 * b1; s[0][2] += a0 * b2; s[0][3] += a0 * b3;
            s[1][0] += a1 * b0; s[1][1] += a1 * b1; s[1][2] += a1 * b2; s[1][3] += a1 * b3;
            s[2][0] += a2 * b0; s[2][1] += a2 * b1; s[2][2] += a2 * b2; s[2][3] += a2 * b3;
            s[3][0] += a3 * b0; s[3][1] += a3 * b1; s[3][2] += a3 * b2; s[3][3] += a3 * b3;
        }
        bool diag = (kt == qt);
        #pragma unroll
        for (int i = 0; i < 4; i++) {
            int qi = ty + 16 * i;
            #pragma unroll
            for (int j = 0; j < 4; j++) {
                int ki = tx + 16 * j;
                float val = s[i][j] * scale;
                if (diag && ki > qi) val = -1e30f;
                Ps[qi * PS_STRIDE + ki] = val;
            }
        }
        __syncthreads();

        // --- online softmax: row q = tid/4, 16 cols per thread ---
        {
            int q = tid >> 2;
            int cc = (tid & 3) * 16;
            float* pr = &Ps[q * PS_STRIDE + cc];
            float mx = -1e30f;
            #pragma unroll
            for (int c = 0; c < 16; c++) mx = fmaxf(mx, pr[c]);
            mx = fmaxf(mx, __shfl_xor_sync(0xffffffffu, mx, 1));
            mx = fmaxf(mx, __shfl_xor_sync(0xffffffffu, mx, 2));
            float m_new = fmaxf(m_r, mx);
            float al = __expf(m_r - m_new);
            float sum = 0.f;
            #pragma unroll
            for (int c = 0; c < 16; c++) {
                float p = __expf(pr[c] - m_new);
                pr[c] = p;
                sum += p;
            }
            sum += __shfl_xor_sync(0xffffffffu, sum, 1);
            sum += __shfl_xor_sync(0xffffffffu, sum, 2);
            l_r = l_r * al + sum;
            m_r = m_new;
            if ((tid & 3) == 0) { alpha_sh[q] = al; l_sh[q] = l_r; }
        }
        __syncthreads();

        // --- rescale + PV accumulate ---
        float av[4];
        #pragma unroll
        for (int i = 0; i < 4; i++) av[i] = alpha_sh[ty + 16 * i];
        #pragma unroll
        for (int i = 0; i < 4; i++)
            #pragma unroll
            for (int j = 0; j < 8; j++) o[i][j] *= av[i];

        #pragma unroll 2
        for (int k = 0; k < 64; k++) {
            float p0 = Ps[(ty +  0) * PS_STRIDE + k];
            float p1 = Ps[(ty + 16) * PS_STRIDE + k];
            float p2 = Ps[(ty + 32) * PS_STRIDE + k];
            float p3 = Ps[(ty + 48) * PS_STRIDE + k];
            float4 v0 = *(float4*)&Vs[k * VS_STRIDE + tx * 8];
            float4 v1 = *(float4*)&Vs[k * VS_STRIDE + tx * 8 + 4];
            o[0][0] += p0 * v0.x; o[0][1] += p0 * v0.y; o[0][2] += p0 * v0.z; o[0][3] += p0 * v0.w;
            o[0][4] += p0 * v1.x; o[0][5] += p0 * v1.y; o[0][6] += p0 * v1.z; o[0][7] += p0 * v1.w;
            o[1][0] += p1 * v0.x; o[1][1] += p1 * v0.y; o[1][2] += p1 * v0.z; o[1][3] += p1 * v0.w;
            o[1][4] += p1 * v1.x; o[1][5] += p1 * v1.y; o[1][6] += p1 * v1.z; o[1][7] += p1 * v1.w;
            o[2][0] += p2 * v0.x; o[2][1] += p2 * v0.y; o[2][2] += p2 * v0.z; o[2][3] += p2 * v0.w;
            o[2][4] += p2 * v1.x; o[2][5] += p2 * v1.y; o[2][6] += p2 * v1.z; o[2][7] += p2 * v1.w;
            o[3][0] += p3 * v0.x; o[3][1] += p3 * v0.y; o[3][2] += p3 * v0.z; o[3][3] += p3 * v0.w;
            o[3][4] += p3 * v1.x; o[3][5] += p3 * v1.y; o[3][6] += p3 * v1.z; o[3][7] += p3 * v1.w;
        }
    }

    // normalize + store
    #pragma unroll
    for (int i = 0; i < 4; i++) {
        int qi = ty + 16 * i;
        float inv = 1.f / l_sh[qi];
        long long off = ((long long)(b * S_LEN + q0 + qi)) * E_DIM + h * D_HEAD + tx * 8;
        *(float4*)&attn_out[off]     = make_float4(o[i][0] * inv, o[i][1] * inv, o[i][2] * inv, o[i][3] * inv);
        *(float4*)&attn_out[off + 4] = make_float4(o[i][4] * inv, o[i][5] * inv, o[i][6] * inv, o[i][7] * inv);
    }
}

// ---------------------------------------------------------------------------
extern "C" void kernel_launch(void* const* d_in, const int* in_sizes, int n_in,
                              void* d_out, int out_size)
{
    const float* hidden   = (const float*)d_in[0];
    const float* qkv_w    = (const float*)d_in[1];
    const float* o_w      = (const float*)d_in[2];
    const float* cosv     = (const float*)d_in[3];
    const float* sinv     = (const float*)d_in[4];
    const int*   blk_tab  = (const int*)d_in[7];

    float* out   = (float*)d_out;                         // [T, E]
    float* out_k = out + (size_t)T_TOK * E_DIM;           // k_cache
    float* out_v = out_k + (size_t)T_TOK * E_DIM;         // v_cache

    float* qkv;  cudaGetSymbolAddress((void**)&qkv,  g_qkv);
    float* attn; cudaGetSymbolAddress((void**)&attn, g_attn);

    // 1) QKV projection: 3 batched GEMMs
    sgemm_kernel<<<dim3(32, 32, 3), 256>>>(hidden, qkv_w, qkv,
                                           T_TOK, E_DIM, E_DIM,
                                           (long long)E_DIM * E_DIM,
                                           (long long)T_TOK * E_DIM);

    // 2) RoPE on q and k
    {
        long long total = 2LL * T_TOK * H_NUM * 64;
        rope_kernel<<<(unsigned)((total + 255) / 256), 256>>>(qkv, cosv, sinv);
    }

    // 3) KV cache scatter (post-RoPE k)
    {
        long long total = (long long)B_SZ * NB_BLK * H_NUM * BS_BLK * D_HEAD;
        cache_write_kernel<<<(unsigned)((total + 255) / 256), 256>>>(qkv, blk_tab, out_k, out_v);
    }

    // 4) Flash attention
    {
        int smem = (64 * QS_STRIDE + 64 * KS_STRIDE + 64 * VS_STRIDE +
                    64 * PS_STRIDE + 64 + 64) * (int)sizeof(float);
        cudaFuncSetAttribute(attn_kernel, cudaFuncAttributeMaxDynamicSharedMemorySize, smem);
        attn_kernel<<<dim3(S_LEN / 64, H_NUM, B_SZ), 256, smem>>>(qkv, attn);
    }

    // 5) Output projection
    sgemm_kernel<<<dim3(32, 32, 1), 256>>>(attn, o_w, out,
                                           T_TOK, E_DIM, E_DIM,
                                           0, 0);
}

// round 6
// speedup vs baseline: 1.2980x; 1.2980x over previous
#include <cuda_runtime.h>
#include <cstdint>

#define T_TOK 4096
#define E_DIM 4096
#define B_SZ  4
#define S_LEN 1024
#define H_NUM 32
#define D_HEAD 128
#define BS_BLK 16
#define NB_BLK 64

// Scratch (allocation-free rule: __device__ globals)
__device__ float g_qkv[3ULL * T_TOK * E_DIM];       // q | k | v, each [T, E]
__device__ float g_attn[(size_t)T_TOK * E_DIM];     // attention output [T, E]
__device__ float g_wt[4ULL * E_DIM * E_DIM];        // transposed weights [4][N][K]

// ===========================================================================
// helpers
// ===========================================================================
__device__ __forceinline__ uint32_t smem_u32(const void* p) {
    uint32_t a;
    asm("{ .reg .u64 t; cvta.to.shared.u64 t, %1; cvt.u32.u64 %0, t; }" : "=r"(a) : "l"(p));
    return a;
}
__device__ __forceinline__ void cp16(uint32_t dst, const void* src) {
    asm volatile("cp.async.ca.shared.global [%0], [%1], 16;" :: "r"(dst), "l"(src));
}
#define CP_COMMIT() asm volatile("cp.async.commit_group;" ::: "memory")
#define CP_WAIT1()  asm volatile("cp.async.wait_group 1;" ::: "memory")

__device__ __forceinline__ void mma_tf32(float* c, const uint32_t* a, const uint32_t* b) {
    asm volatile(
        "mma.sync.aligned.m16n8k8.row.col.f32.tf32.tf32.f32 "
        "{%0,%1,%2,%3}, {%4,%5,%6,%7}, {%8,%9}, {%0,%1,%2,%3};"
        : "+f"(c[0]), "+f"(c[1]), "+f"(c[2]), "+f"(c[3])
        : "r"(a[0]), "r"(a[1]), "r"(a[2]), "r"(a[3]), "r"(b[0]), "r"(b[1]));
}
__device__ __forceinline__ uint32_t f2tf32(float x) {
    uint32_t r;
    asm("cvt.rna.tf32.f32 %0, %1;" : "=r"(r) : "f"(x));
    return r;
}

// ===========================================================================
// Weight transpose: W[z][k][n] -> Wt[z][n][k]   (z: 0..2 qkv, 3 = o_proj)
// ===========================================================================
__global__ void transpose_kernel(const float* __restrict__ qkv_w,
                                 const float* __restrict__ o_w,
                                 float* __restrict__ out)
{
    __shared__ float tile[32][33];
    int z = blockIdx.z;
    const float* src = (z < 3) ? qkv_w + (size_t)z * E_DIM * E_DIM : o_w;
    float* dst = out + (size_t)z * E_DIM * E_DIM;
    int k0 = blockIdx.y * 32, n0 = blockIdx.x * 32;
    int tx = threadIdx.x, ty = threadIdx.y;
    #pragma unroll
    for (int j = 0; j < 32; j += 8)
        tile[ty + j][tx] = src[(size_t)(k0 + ty + j) * E_DIM + n0 + tx];
    __syncthreads();
    #pragma unroll
    for (int j = 0; j < 32; j += 8)
        dst[(size_t)(n0 + ty + j) * E_DIM + k0 + tx] = tile[tx][ty + j];
}

// ===========================================================================
// 3xTF32 mma.sync GEMM: C[z][m][n] = sum_k A[m][k] * Bt[z][n][k]
// Block tile 128x128, K-tile 16, 8 warps (2Mx4N), warp tile 64x32.
// Each fp32 operand split into hi/lo tf32; 3 MMAs recover ~fp32 accuracy.
// 3-stage cp.async pipeline. Smem row stride 20 floats (conflict-free).
// ===========================================================================
#define KT 16
#define NK_ITERS (E_DIM / KT)            // 256
#define ROW_F 20                         // floats per smem row (16 + 4 pad)
#define TILE_BYTES_G (128 * ROW_F * 4)   // 10240 per matrix per stage
#define STAGE_BYTES_G (2 * TILE_BYTES_G) // 20480
#define NSTAGES 3
#define GEMM_SMEM (NSTAGES * STAGE_BYTES_G)   // 61440

__device__ __forceinline__ void stage_load(uint32_t smb, int st,
                                           const float* __restrict__ Ag,
                                           const float* __restrict__ Bg,
                                           int k0, int tid)
{
    int row = tid >> 1;
    int half = tid & 1;
    uint32_t base = smb + st * STAGE_BYTES_G + row * (ROW_F * 4) + half * 32;
    const float* asrc = Ag + (long long)row * E_DIM + k0 + half * 8;
    cp16(base, asrc);
    cp16(base + 16, asrc + 4);
    const float* bsrc = Bg + (long long)row * E_DIM + k0 + half * 8;
    cp16(base + TILE_BYTES_G, bsrc);
    cp16(base + TILE_BYTES_G + 16, bsrc + 4);
}

__global__ __launch_bounds__(256, 1)
void gemm_mma_kernel(const float* __restrict__ A, const float* __restrict__ Bt,
                     float* __restrict__ C, long long strideB, long long strideC)
{
    extern __shared__ char sm[];
    uint32_t smb = smem_u32(sm);
    const int tid = threadIdx.x;
    const int wid = tid >> 5;
    const int lane = tid & 31;
    const int grp = lane >> 2;       // 0..7
    const int thr = lane & 3;        // 0..3
    const int warp_m = wid >> 2;     // 0..1
    const int warp_n = wid & 3;      // 0..3

    const int m0 = blockIdx.y * 128;
    const int n0 = blockIdx.x * 128;
    const float* Ag = A + (long long)m0 * E_DIM;
    const float* Bg = Bt + (long long)blockIdx.z * strideB + (long long)n0 * E_DIM;
    float* Cg = C + (long long)blockIdx.z * strideC;

    float acc[4][4][4];
    #pragma unroll
    for (int mi = 0; mi < 4; mi++)
        #pragma unroll
        for (int ni = 0; ni < 4; ni++)
            #pragma unroll
            for (int q = 0; q < 4; q++) acc[mi][ni][q] = 0.f;

    // prologue: stages 0, 1
    stage_load(smb, 0, Ag, Bg, 0, tid);
    CP_COMMIT();
    stage_load(smb, 1, Ag, Bg, KT, tid);
    CP_COMMIT();

    int st = 0;
    for (int kt = 0; kt < NK_ITERS; ++kt) {
        CP_WAIT1();
        __syncthreads();
        if (kt + 2 < NK_ITERS) {
            int nst = st + 2; if (nst >= NSTAGES) nst -= NSTAGES;
            stage_load(smb, nst, Ag, Bg, (kt + 2) * KT, tid);
        }
        CP_COMMIT();   // keep group count in lockstep even when no loads issued

        const float* Af = (const float*)(sm + st * STAGE_BYTES_G);
        const float* Bf = (const float*)(sm + st * STAGE_BYTES_G + TILE_BYTES_G);

        #pragma unroll
        for (int ks = 0; ks < 2; ++ks) {
            int c0 = ks * 8 + thr;
            uint32_t ahi[4][4], alo[4][4], bhi[4][2], blo[4][2];
            #pragma unroll
            for (int mi = 0; mi < 4; mi++) {
                int r = warp_m * 64 + mi * 16 + grp;
                float v0 = Af[r * ROW_F + c0];
                float v1 = Af[(r + 8) * ROW_F + c0];
                float v2 = Af[r * ROW_F + c0 + 4];
                float v3 = Af[(r + 8) * ROW_F + c0 + 4];
                ahi[mi][0] = f2tf32(v0); alo[mi][0] = f2tf32(v0 - __uint_as_float(ahi[mi][0]));
                ahi[mi][1] = f2tf32(v1); alo[mi][1] = f2tf32(v1 - __uint_as_float(ahi[mi][1]));
                ahi[mi][2] = f2tf32(v2); alo[mi][2] = f2tf32(v2 - __uint_as_float(ahi[mi][2]));
                ahi[mi][3] = f2tf32(v3); alo[mi][3] = f2tf32(v3 - __uint_as_float(ahi[mi][3]));
            }
            #pragma unroll
            for (int ni = 0; ni < 4; ni++) {
                int nb = warp_n * 32 + ni * 8 + grp;
                float w0 = Bf[nb * ROW_F + c0];
                float w1 = Bf[nb * ROW_F + c0 + 4];
                bhi[ni][0] = f2tf32(w0); blo[ni][0] = f2tf32(w0 - __uint_as_float(bhi[ni][0]));
                bhi[ni][1] = f2tf32(w1); blo[ni][1] = f2tf32(w1 - __uint_as_float(bhi[ni][1]));
            }
            #pragma unroll
            for (int mi = 0; mi < 4; mi++)
                #pragma unroll
                for (int ni = 0; ni < 4; ni++) {
                    mma_tf32(acc[mi][ni], alo[mi], bhi[ni]);
                    mma_tf32(acc[mi][ni], ahi[mi], blo[ni]);
                    mma_tf32(acc[mi][ni], ahi[mi], bhi[ni]);
                }
        }

        st = st + 1; if (st >= NSTAGES) st = 0;
        __syncthreads();
    }

    // epilogue: direct global stores (float2 per accumulator pair)
    #pragma unroll
    for (int mi = 0; mi < 4; mi++) {
        long long r0 = m0 + warp_m * 64 + mi * 16 + grp;
        #pragma unroll
        for (int ni = 0; ni < 4; ni++) {
            long long col = n0 + warp_n * 32 + ni * 8 + thr * 2;
            *(float2*)&Cg[r0 * E_DIM + col]       = make_float2(acc[mi][ni][0], acc[mi][ni][1]);
            *(float2*)&Cg[(r0 + 8) * E_DIM + col] = make_float2(acc[mi][ni][2], acc[mi][ni][3]);
        }
    }
}

// ===========================================================================
// RoPE (in-place on q and k slices of g_qkv)
// ===========================================================================
__global__ void rope_kernel(float* __restrict__ qkv,
                            const float* __restrict__ cosv,
                            const float* __restrict__ sinv)
{
    long long idx = (long long)blockIdx.x * blockDim.x + threadIdx.x;
    if (idx >= 2LL * T_TOK * H_NUM * 64) return;
    int j = idx & 63;
    int h = (idx >> 6) & (H_NUM - 1);
    long long t = (idx >> 11) & (T_TOK - 1);
    int which = (int)(idx >> 23);   // 0 = q, 1 = k
    float* base = qkv + (long long)which * T_TOK * E_DIM + t * E_DIM + h * D_HEAD;
    float c = cosv[t * 64 + j];
    float s = sinv[t * 64 + j];
    float x1 = base[j];
    float x2 = base[j + 64];
    base[j]      = x1 * c - x2 * s;
    base[j + 64] = x2 * c + x1 * s;
}

// ===========================================================================
// KV cache scatter
// ===========================================================================
__global__ void cache_write_kernel(const float* __restrict__ qkv,
                                   const int* __restrict__ block_tables,
                                   float* __restrict__ out_k,
                                   float* __restrict__ out_v)
{
    long long idx = (long long)blockIdx.x * blockDim.x + threadIdx.x;
    if (idx >= (long long)B_SZ * NB_BLK * H_NUM * BS_BLK * D_HEAD) return;
    int d  = idx & 127;
    int bs = (idx >> 7) & (BS_BLK - 1);
    int h  = (idx >> 11) & (H_NUM - 1);
    long long nbb = idx >> 16;
    int b  = (int)(nbb >> 6);
    int nb = (int)(nbb & 63);
    int blk = block_tables[b * NB_BLK + nb];
    long long t = (long long)b * S_LEN + nb * BS_BLK + bs;
    long long src = t * E_DIM + h * D_HEAD + d;
    long long dst = (((long long)blk * H_NUM + h) * BS_BLK + bs) * D_HEAD + d;
    out_k[dst] = qkv[(long long)T_TOK * E_DIM + src];
    out_v[dst] = qkv[2LL * T_TOK * E_DIM + src];
}

// ===========================================================================
// Flash attention, fp32, causal (unchanged from R1 — passing)
// ===========================================================================
#define QS_STRIDE 129
#define KS_STRIDE 129
#define VS_STRIDE 132
#define PS_STRIDE 65

__global__ __launch_bounds__(256, 1)
void attn_kernel(const float* __restrict__ qkv, float* __restrict__ attn_out)
{
    extern __shared__ float smf[];
    float* Qs = smf;
    float* Ks = Qs + 64 * QS_STRIDE;
    float* Vs = Ks + 64 * KS_STRIDE;
    float* Ps = Vs + 64 * VS_STRIDE;
    float* alpha_sh = Ps + 64 * PS_STRIDE;
    float* l_sh = alpha_sh + 64;

    int tid = threadIdx.x;
    int tx = tid & 15, ty = tid >> 4;
    int qt = blockIdx.x, h = blockIdx.y, b = blockIdx.z;
    int q0 = qt * 64;

    const long long TE = (long long)T_TOK * E_DIM;
    const float* qbase = qkv;
    const float* kbase = qkv + TE;
    const float* vbase = qkv + 2 * TE;
    const float scale = 0.08838834764831845f;

    for (int c = tid; c < 64 * 32; c += 256) {
        int row = c >> 5;
        int c4 = (c & 31) * 4;
        float4 v = *(const float4*)&qbase[((long long)(b * S_LEN + q0 + row)) * E_DIM + h * D_HEAD + c4];
        Qs[row * QS_STRIDE + c4]     = v.x;
        Qs[row * QS_STRIDE + c4 + 1] = v.y;
        Qs[row * QS_STRIDE + c4 + 2] = v.z;
        Qs[row * QS_STRIDE + c4 + 3] = v.w;
    }

    float m_r = -1e30f, l_r = 0.f;
    float o[4][8];
    #pragma unroll
    for (int i = 0; i < 4; i++)
        #pragma unroll
        for (int j = 0; j < 8; j++) o[i][j] = 0.f;

    int nkt = qt + 1;
    for (int kt = 0; kt < nkt; kt++) {
        int k0 = kt * 64;
        __syncthreads();
        for (int c = tid; c < 64 * 32; c += 256) {
            int row = c >> 5;
            int c4 = (c & 31) * 4;
            long long goff = ((long long)(b * S_LEN + k0 + row)) * E_DIM + h * D_HEAD + c4;
            float4 kv = *(const float4*)&kbase[goff];
            Ks[row * KS_STRIDE + c4]     = kv.x;
            Ks[row * KS_STRIDE + c4 + 1] = kv.y;
            Ks[row * KS_STRIDE + c4 + 2] = kv.z;
            Ks[row * KS_STRIDE + c4 + 3] = kv.w;
            float4 vv = *(const float4*)&vbase[goff];
            *(float4*)&Vs[row * VS_STRIDE + c4] = vv;
        }
        __syncthreads();

        float s[4][4];
        #pragma unroll
        for (int i = 0; i < 4; i++)
            #pragma unroll
            for (int j = 0; j < 4; j++) s[i][j] = 0.f;
        const float* qr0 = &Qs[(ty +  0) * QS_STRIDE];
        const float* qr1 = &Qs[(ty + 16) * QS_STRIDE];
        const float* qr2 = &Qs[(ty + 32) * QS_STRIDE];
        const float* qr3 = &Qs[(ty + 48) * QS_STRIDE];
        const float* kr0 = &Ks[(tx +  0) * KS_STRIDE];
        const float* kr1 = &Ks[(tx + 16) * KS_STRIDE];
        const float* kr2 = &Ks[(tx + 32) * KS_STRIDE];
        const float* kr3 = &Ks[(tx + 48) * KS_STRIDE];
        #pragma unroll 4
        for (int d = 0; d < 128; d++) {
            float a0 = qr0[d], a1 = qr1[d], a2 = qr2[d], a3 = qr3[d];
            float b0 = kr0[d], b1 = kr1[d], b2 = kr2[d], b3 = kr3[d];
            s[0][0] += a0 * b0; s[0][1] += a0 * b1; s[0][2] += a0 * b2; s[0][3] += a0 * b3;
            s[1][0] += a1 * b0; s[1][1] += a1 * b1; s[1][2] += a1 * b2; s[1][3] += a1 * b3;
            s[2][0] += a2 * b0; s[2][1] += a2 * b1; s[2][2] += a2 * b2; s[2][3] += a2 * b3;
            s[3][0] += a3 * b0; s[3][1] += a3 * b1; s[3][2] += a3 * b2; s[3][3] += a3 * b3;
        }
        bool diag = (kt == qt);
        #pragma unroll
        for (int i = 0; i < 4; i++) {
            int qi = ty + 16 * i;
            #pragma unroll
            for (int j = 0; j < 4; j++) {
                int ki = tx + 16 * j;
                float val = s[i][j] * scale;
                if (diag && ki > qi) val = -1e30f;
                Ps[qi * PS_STRIDE + ki] = val;
            }
        }
        __syncthreads();

        {
            int q = tid >> 2;
            int cc = (tid & 3) * 16;
            float* pr = &Ps[q * PS_STRIDE + cc];
            float mx = -1e30f;
            #pragma unroll
            for (int c = 0; c < 16; c++) mx = fmaxf(mx, pr[c]);
            mx = fmaxf(mx, __shfl_xor_sync(0xffffffffu, mx, 1));
            mx = fmaxf(mx, __shfl_xor_sync(0xffffffffu, mx, 2));
            float m_new = fmaxf(m_r, mx);
            float al = __expf(m_r - m_new);
            float sum = 0.f;
            #pragma unroll
            for (int c = 0; c < 16; c++) {
                float p = __expf(pr[c] - m_new);
                pr[c] = p;
                sum += p;
            }
            sum += __shfl_xor_sync(0xffffffffu, sum, 1);
            sum += __shfl_xor_sync(0xffffffffu, sum, 2);
            l_r = l_r * al + sum;
            m_r = m_new;
            if ((tid & 3) == 0) { alpha_sh[q] = al; l_sh[q] = l_r; }
        }
        __syncthreads();

        float av[4];
        #pragma unroll
        for (int i = 0; i < 4; i++) av[i] = alpha_sh[ty + 16 * i];
        #pragma unroll
        for (int i = 0; i < 4; i++)
            #pragma unroll
            for (int j = 0; j < 8; j++) o[i][j] *= av[i];

        #pragma unroll 2
        for (int k = 0; k < 64; k++) {
            float p0 = Ps[(ty +  0) * PS_STRIDE + k];
            float p1 = Ps[(ty + 16) * PS_STRIDE + k];
            float p2 = Ps[(ty + 32) * PS_STRIDE + k];
            float p3 = Ps[(ty + 48) * PS_STRIDE + k];
            float4 v0 = *(float4*)&Vs[k * VS_STRIDE + tx * 8];
            float4 v1 = *(float4*)&Vs[k * VS_STRIDE + tx * 8 + 4];
            o[0][0] += p0 * v0.x; o[0][1] += p0 * v0.y; o[0][2] += p0 * v0.z; o[0][3] += p0 * v0.w;
            o[0][4] += p0 * v1.x; o[0][5] += p0 * v1.y; o[0][6] += p0 * v1.z; o[0][7] += p0 * v1.w;
            o[1][0] += p1 * v0.x; o[1][1] += p1 * v0.y; o[1][2] += p1 * v0.z; o[1][3] += p1 * v0.w;
            o[1][4] += p1 * v1.x; o[1][5] += p1 * v1.y; o[1][6] += p1 * v1.z; o[1][7] += p1 * v1.w;
            o[2][0] += p2 * v0.x; o[2][1] += p2 * v0.y; o[2][2] += p2 * v0.z; o[2][3] += p2 * v0.w;
            o[2][4] += p2 * v1.x; o[2][5] += p2 * v1.y; o[2][6] += p2 * v1.z; o[2][7] += p2 * v1.w;
            o[3][0] += p3 * v0.x; o[3][1] += p3 * v0.y; o[3][2] += p3 * v0.z; o[3][3] += p3 * v0.w;
            o[3][4] += p3 * v1.x; o[3][5] += p3 * v1.y; o[3][6] += p3 * v1.z; o[3][7] += p3 * v1.w;
        }
    }

    #pragma unroll
    for (int i = 0; i < 4; i++) {
        int qi = ty + 16 * i;
        float inv = 1.f / l_sh[qi];
        long long off = ((long long)(b * S_LEN + q0 + qi)) * E_DIM + h * D_HEAD + tx * 8;
        *(float4*)&attn_out[off]     = make_float4(o[i][0] * inv, o[i][1] * inv, o[i][2] * inv, o[i][3] * inv);
        *(float4*)&attn_out[off + 4] = make_float4(o[i][4] * inv, o[i][5] * inv, o[i][6] * inv, o[i][7] * inv);
    }
}

// ===========================================================================
extern "C" void kernel_launch(void* const* d_in, const int* in_sizes, int n_in,
                              void* d_out, int out_size)
{
    const float* hidden   = (const float*)d_in[0];
    const float* qkv_w    = (const float*)d_in[1];
    const float* o_w      = (const float*)d_in[2];
    const float* cosv     = (const float*)d_in[3];
    const float* sinv     = (const float*)d_in[4];
    const int*   blk_tab  = (const int*)d_in[7];

    float* out   = (float*)d_out;
    float* out_k = out + (size_t)T_TOK * E_DIM;
    float* out_v = out_k + (size_t)T_TOK * E_DIM;

    float* qkv;  cudaGetSymbolAddress((void**)&qkv,  g_qkv);
    float* attn; cudaGetSymbolAddress((void**)&attn, g_attn);
    float* wt;   cudaGetSymbolAddress((void**)&wt,   g_wt);

    // 0) Transpose weights: [K,N] -> [N,K] for all 4 matrices
    transpose_kernel<<<dim3(E_DIM / 32, E_DIM / 32, 4), dim3(32, 8)>>>(qkv_w, o_w, wt);

    // 1) QKV projection (3xTF32 mma.sync)
    cudaFuncSetAttribute(gemm_mma_kernel, cudaFuncAttributeMaxDynamicSharedMemorySize, GEMM_SMEM);
    gemm_mma_kernel<<<dim3(E_DIM / 128, T_TOK / 128, 3), 256, GEMM_SMEM>>>(
        hidden, wt, qkv, (long long)E_DIM * E_DIM, (long long)T_TOK * E_DIM);

    // 2) RoPE on q and k
    {
        long long total = 2LL * T_TOK * H_NUM * 64;
        rope_kernel<<<(unsigned)((total + 255) / 256), 256>>>(qkv, cosv, sinv);
    }

    // 3) KV cache scatter
    {
        long long total = (long long)B_SZ * NB_BLK * H_NUM * BS_BLK * D_HEAD;
        cache_write_kernel<<<(unsigned)((total + 255) / 256), 256>>>(qkv, blk_tab, out_k, out_v);
    }

    // 4) Flash attention (fp32)
    {
        int smem = (64 * QS_STRIDE + 64 * KS_STRIDE + 64 * VS_STRIDE +
                    64 * PS_STRIDE + 64 + 64) * (int)sizeof(float);
        cudaFuncSetAttribute(attn_kernel, cudaFuncAttributeMaxDynamicSharedMemorySize, smem);
        attn_kernel<<<dim3(S_LEN / 64, H_NUM, B_SZ), 256, smem>>>(qkv, attn);
    }

    // 5) Output projection (3xTF32 mma.sync)
    gemm_mma_kernel<<<dim3(E_DIM / 128, T_TOK / 128, 1), 256, GEMM_SMEM>>>(
        attn, wt + 3ULL * E_DIM * E_DIM, out, 0, 0);
}

// round 7
// speedup vs baseline: 1.7795x; 1.3710x over previous
#include <cuda_runtime.h>
#include <cuda_fp16.h>
#include <cstdint>

#define T_TOK 4096
#define E_DIM 4096
#define B_SZ  4
#define S_LEN 1024
#define H_NUM 32
#define D_HEAD 128
#define BS_BLK 16
#define NB_BLK 64

// Scratch (allocation-free rule: __device__ globals)
__device__ float  g_qkv[3ULL * T_TOK * E_DIM];        // q | k | v, each [T, E] fp32
__device__ __half g_wt_hi[4ULL * E_DIM * E_DIM];      // transposed weight hi planes [4][N][K]
__device__ __half g_wt_lo[4ULL * E_DIM * E_DIM];      // transposed weight lo planes
__device__ __half g_ahi[(size_t)T_TOK * E_DIM];       // activation hi plane [T, E]
__device__ __half g_alo[(size_t)T_TOK * E_DIM];       // activation lo plane

// ===========================================================================
// helpers
// ===========================================================================
__device__ __forceinline__ uint32_t smem_u32(const void* p) {
    uint32_t a;
    asm("{ .reg .u64 t; cvta.to.shared.u64 t, %1; cvt.u32.u64 %0, t; }" : "=r"(a) : "l"(p));
    return a;
}
__device__ __forceinline__ void cp16(uint32_t dst, const void* src) {
    asm volatile("cp.async.ca.shared.global [%0], [%1], 16;" :: "r"(dst), "l"(src));
}
#define CP_COMMIT() asm volatile("cp.async.commit_group;" ::: "memory")
#define CP_WAIT2()  asm volatile("cp.async.wait_group 2;" ::: "memory")

__device__ __forceinline__ void mma_f16(float* c, const uint32_t* a, const uint32_t* b) {
    asm volatile(
        "mma.sync.aligned.m16n8k16.row.col.f32.f16.f16.f32 "
        "{%0,%1,%2,%3}, {%4,%5,%6,%7}, {%8,%9}, {%0,%1,%2,%3};"
        : "+f"(c[0]), "+f"(c[1]), "+f"(c[2]), "+f"(c[3])
        : "r"(a[0]), "r"(a[1]), "r"(a[2]), "r"(a[3]), "r"(b[0]), "r"(b[1]));
}

// ===========================================================================
// Weight transpose + hi/lo split: W[z][k][n] fp32 -> Wt_hi/lo[z][n][k] half
// ===========================================================================
__global__ void transpose_split_kernel(const float* __restrict__ qkv_w,
                                       const float* __restrict__ o_w,
                                       __half* __restrict__ out_hi,
                                       __half* __restrict__ out_lo)
{
    __shared__ float tile[32][33];
    int z = blockIdx.z;
    const float* src = (z < 3) ? qkv_w + (size_t)z * E_DIM * E_DIM : o_w;
    __half* dhi = out_hi + (size_t)z * E_DIM * E_DIM;
    __half* dlo = out_lo + (size_t)z * E_DIM * E_DIM;
    int k0 = blockIdx.y * 32, n0 = blockIdx.x * 32;
    int tx = threadIdx.x, ty = threadIdx.y;
    #pragma unroll
    for (int j = 0; j < 32; j += 8)
        tile[ty + j][tx] = src[(size_t)(k0 + ty + j) * E_DIM + n0 + tx];
    __syncthreads();
    #pragma unroll
    for (int j = 0; j < 32; j += 8) {
        float x = tile[tx][ty + j];
        __half hi = __float2half_rn(x);
        __half lo = __float2half_rn(x - __half2float(hi));
        size_t off = (size_t)(n0 + ty + j) * E_DIM + k0 + tx;
        dhi[off] = hi;
        dlo[off] = lo;
    }
}

// ===========================================================================
// Activation hi/lo split: X[T,E] fp32 -> hi/lo half planes
// ===========================================================================
__global__ void split_a_kernel(const float* __restrict__ x,
                               __half* __restrict__ xhi, __half* __restrict__ xlo)
{
    long long i = ((long long)blockIdx.x * blockDim.x + threadIdx.x) * 4;
    if (i >= (long long)T_TOK * E_DIM) return;
    float4 v = *(const float4*)&x[i];
    __half h0 = __float2half_rn(v.x), h1 = __float2half_rn(v.y);
    __half h2 = __float2half_rn(v.z), h3 = __float2half_rn(v.w);
    __half l0 = __float2half_rn(v.x - __half2float(h0));
    __half l1 = __float2half_rn(v.y - __half2float(h1));
    __half l2 = __float2half_rn(v.z - __half2float(h2));
    __half l3 = __float2half_rn(v.w - __half2float(h3));
    *(half2*)&xhi[i]     = __halves2half2(h0, h1);
    *(half2*)&xhi[i + 2] = __halves2half2(h2, h3);
    *(half2*)&xlo[i]     = __halves2half2(l0, l1);
    *(half2*)&xlo[i + 2] = __halves2half2(l2, l3);
}

// ===========================================================================
// fp16 hi/lo split GEMM: C[z][m][n] = sum_k A[m][k] * Bt[z][n][k]  (fp32 out)
// Block tile 128x128, K-tile 16, 8 warps (2Mx4N), warp tile 64x32.
// Row layout per stage: 128 rows x 80B  (hi 32B | lo 32B | 16B pad) per matrix.
// Word stride 20 => conflict-free fragment LDS. 4-stage cp.async pipeline.
// ===========================================================================
#define KT 16
#define NK_ITERS (E_DIM / KT)              // 256
#define ROW_B 80                           // bytes per row
#define TILE_B (128 * ROW_B)               // 10240 per matrix per stage
#define STAGE_B (2 * TILE_B)               // 20480
#define NSTAGES 4
#define GEMM_SMEM (NSTAGES * STAGE_B)      // 81920

__device__ __forceinline__ void stage_load(uint32_t smb, int st,
                                           const __half* __restrict__ Ahi,
                                           const __half* __restrict__ Alo,
                                           const __half* __restrict__ Bhi,
                                           const __half* __restrict__ Blo,
                                           int k0, int tid)
{
    // 1024 cp16 jobs: idx -> matrix(1b) | row(7b) | seg(2b)
    #pragma unroll
    for (int j = 0; j < 4; ++j) {
        int idx = tid + 256 * j;
        int m   = idx >> 9;
        int r   = (idx >> 2) & 127;
        int seg = idx & 3;                 // 0,1 = hi halves 0-7 / 8-15 ; 2,3 = lo
        uint32_t dst = smb + st * STAGE_B + m * TILE_B + r * ROW_B + seg * 16;
        const __half* hp = m ? Bhi : Ahi;
        const __half* lp = m ? Blo : Alo;
        const __half* src = (seg < 2 ? hp : lp) + (long long)r * E_DIM + k0 + (seg & 1) * 8;
        cp16(dst, src);
    }
}

__global__ __launch_bounds__(256, 1)
void gemm_mma_kernel(const __half* __restrict__ Ahi, const __half* __restrict__ Alo,
                     const __half* __restrict__ Bhi, const __half* __restrict__ Blo,
                     float* __restrict__ C, long long strideB, long long strideC)
{
    extern __shared__ char sm[];
    uint32_t smb = smem_u32(sm);
    const int tid = threadIdx.x;
    const int wid = tid >> 5;
    const int lane = tid & 31;
    const int grp = lane >> 2;       // 0..7
    const int thr = lane & 3;        // 0..3
    const int warp_m = wid >> 2;     // 0..1
    const int warp_n = wid & 3;      // 0..3

    const int m0 = blockIdx.y * 128;
    const int n0 = blockIdx.x * 128;
    const __half* Ah = Ahi + (long long)m0 * E_DIM;
    const __half* Al = Alo + (long long)m0 * E_DIM;
    const __half* Bh = Bhi + (long long)blockIdx.z * strideB + (long long)n0 * E_DIM;
    const __half* Bl = Blo + (long long)blockIdx.z * strideB + (long long)n0 * E_DIM;
    float* Cg = C + (long long)blockIdx.z * strideC;

    float acc[4][4][4];
    #pragma unroll
    for (int mi = 0; mi < 4; mi++)
        #pragma unroll
        for (int ni = 0; ni < 4; ni++)
            #pragma unroll
            for (int q = 0; q < 4; q++) acc[mi][ni][q] = 0.f;

    // prologue: stages 0,1,2
    stage_load(smb, 0, Ah, Al, Bh, Bl, 0, tid);       CP_COMMIT();
    stage_load(smb, 1, Ah, Al, Bh, Bl, KT, tid);      CP_COMMIT();
    stage_load(smb, 2, Ah, Al, Bh, Bl, 2 * KT, tid);  CP_COMMIT();

    for (int kt = 0; kt < NK_ITERS; ++kt) {
        int st = kt & 3;
        CP_WAIT2();
        __syncthreads();

        if (kt + 3 < NK_ITERS) {
            stage_load(smb, (kt + 3) & 3, Ah, Al, Bh, Bl, (kt + 3) * KT, tid);
        }
        CP_COMMIT();

        const uint32_t* W  = (const uint32_t*)(sm + st * STAGE_B);
        const uint32_t* WB = W + TILE_B / 4;

        uint32_t ah[4][4], al[4][4], bh[4][2], bl[4][2];
        #pragma unroll
        for (int mi = 0; mi < 4; mi++) {
            int r = warp_m * 64 + mi * 16 + grp;
            int w0 = r * 20 + thr;
            int w1 = (r + 8) * 20 + thr;
            ah[mi][0] = W[w0];      ah[mi][1] = W[w1];
            ah[mi][2] = W[w0 + 4];  ah[mi][3] = W[w1 + 4];
            al[mi][0] = W[w0 + 8];  al[mi][1] = W[w1 + 8];
            al[mi][2] = W[w0 + 12]; al[mi][3] = W[w1 + 12];
        }
        #pragma unroll
        for (int ni = 0; ni < 4; ni++) {
            int nb = warp_n * 32 + ni * 8 + grp;
            int w0 = nb * 20 + thr;
            bh[ni][0] = WB[w0];     bh[ni][1] = WB[w0 + 4];
            bl[ni][0] = WB[w0 + 8]; bl[ni][1] = WB[w0 + 12];
        }
        #pragma unroll
        for (int mi = 0; mi < 4; mi++)
            #pragma unroll
            for (int ni = 0; ni < 4; ni++) {
                mma_f16(acc[mi][ni], al[mi], bh[ni]);
                mma_f16(acc[mi][ni], ah[mi], bl[ni]);
                mma_f16(acc[mi][ni], ah[mi], bh[ni]);
            }
        __syncthreads();
    }

    // epilogue: direct global stores
    #pragma unroll
    for (int mi = 0; mi < 4; mi++) {
        long long r0 = m0 + warp_m * 64 + mi * 16 + grp;
        #pragma unroll
        for (int ni = 0; ni < 4; ni++) {
            long long col = n0 + warp_n * 32 + ni * 8 + thr * 2;
            *(float2*)&Cg[r0 * E_DIM + col]       = make_float2(acc[mi][ni][0], acc[mi][ni][1]);
            *(float2*)&Cg[(r0 + 8) * E_DIM + col] = make_float2(acc[mi][ni][2], acc[mi][ni][3]);
        }
    }
}

// ===========================================================================
// RoPE (in-place on q and k slices of g_qkv)
// ===========================================================================
__global__ void rope_kernel(float* __restrict__ qkv,
                            const float* __restrict__ cosv,
                            const float* __restrict__ sinv)
{
    long long idx = (long long)blockIdx.x * blockDim.x + threadIdx.x;
    if (idx >= 2LL * T_TOK * H_NUM * 64) return;
    int j = idx & 63;
    int h = (idx >> 6) & (H_NUM - 1);
    long long t = (idx >> 11) & (T_TOK - 1);
    int which = (int)(idx >> 23);   // 0 = q, 1 = k
    float* base = qkv + (long long)which * T_TOK * E_DIM + t * E_DIM + h * D_HEAD;
    float c = cosv[t * 64 + j];
    float s = sinv[t * 64 + j];
    float x1 = base[j];
    float x2 = base[j + 64];
    base[j]      = x1 * c - x2 * s;
    base[j + 64] = x2 * c + x1 * s;
}

// ===========================================================================
// KV cache scatter
// ===========================================================================
__global__ void cache_write_kernel(const float* __restrict__ qkv,
                                   const int* __restrict__ block_tables,
                                   float* __restrict__ out_k,
                                   float* __restrict__ out_v)
{
    long long idx = (long long)blockIdx.x * blockDim.x + threadIdx.x;
    if (idx >= (long long)B_SZ * NB_BLK * H_NUM * BS_BLK * D_HEAD) return;
    int d  = idx & 127;
    int bs = (idx >> 7) & (BS_BLK - 1);
    int h  = (idx >> 11) & (H_NUM - 1);
    long long nbb = idx >> 16;
    int b  = (int)(nbb >> 6);
    int nb = (int)(nbb & 63);
    int blk = block_tables[b * NB_BLK + nb];
    long long t = (long long)b * S_LEN + nb * BS_BLK + bs;
    long long src = t * E_DIM + h * D_HEAD + d;
    long long dst = (((long long)blk * H_NUM + h) * BS_BLK + bs) * D_HEAD + d;
    out_k[dst] = qkv[(long long)T_TOK * E_DIM + src];
    out_v[dst] = qkv[2LL * T_TOK * E_DIM + src];
}

// ===========================================================================
// Flash attention, fp32, causal. Writes hi/lo half planes for the O-proj GEMM.
// ===========================================================================
#define QS_STRIDE 129
#define KS_STRIDE 129
#define VS_STRIDE 132
#define PS_STRIDE 65

__global__ __launch_bounds__(256, 1)
void attn_kernel(const float* __restrict__ qkv,
                 __half* __restrict__ ohi, __half* __restrict__ olo)
{
    extern __shared__ float smf[];
    float* Qs = smf;
    float* Ks = Qs + 64 * QS_STRIDE;
    float* Vs = Ks + 64 * KS_STRIDE;
    float* Ps = Vs + 64 * VS_STRIDE;
    float* alpha_sh = Ps + 64 * PS_STRIDE;
    float* l_sh = alpha_sh + 64;

    int tid = threadIdx.x;
    int tx = tid & 15, ty = tid >> 4;
    int qt = blockIdx.x, h = blockIdx.y, b = blockIdx.z;
    int q0 = qt * 64;

    const long long TE = (long long)T_TOK * E_DIM;
    const float* qbase = qkv;
    const float* kbase = qkv + TE;
    const float* vbase = qkv + 2 * TE;
    const float scale = 0.08838834764831845f;

    for (int c = tid; c < 64 * 32; c += 256) {
        int row = c >> 5;
        int c4 = (c & 31) * 4;
        float4 v = *(const float4*)&qbase[((long long)(b * S_LEN + q0 + row)) * E_DIM + h * D_HEAD + c4];
        Qs[row * QS_STRIDE + c4]     = v.x;
        Qs[row * QS_STRIDE + c4 + 1] = v.y;
        Qs[row * QS_STRIDE + c4 + 2] = v.z;
        Qs[row * QS_STRIDE + c4 + 3] = v.w;
    }

    float m_r = -1e30f, l_r = 0.f;
    float o[4][8];
    #pragma unroll
    for (int i = 0; i < 4; i++)
        #pragma unroll
        for (int j = 0; j < 8; j++) o[i][j] = 0.f;

    int nkt = qt + 1;
    for (int kt = 0; kt < nkt; kt++) {
        int k0 = kt * 64;
        __syncthreads();
        for (int c = tid; c < 64 * 32; c += 256) {
            int row = c >> 5;
            int c4 = (c & 31) * 4;
            long long goff = ((long long)(b * S_LEN + k0 + row)) * E_DIM + h * D_HEAD + c4;
            float4 kv = *(const float4*)&kbase[goff];
            Ks[row * KS_STRIDE + c4]     = kv.x;
            Ks[row * KS_STRIDE + c4 + 1] = kv.y;
            Ks[row * KS_STRIDE + c4 + 2] = kv.z;
            Ks[row * KS_STRIDE + c4 + 3] = kv.w;
            float4 vv = *(const float4*)&vbase[goff];
            *(float4*)&Vs[row * VS_STRIDE + c4] = vv;
        }
        __syncthreads();

        float s[4][4];
        #pragma unroll
        for (int i = 0; i < 4; i++)
            #pragma unroll
            for (int j = 0; j < 4; j++) s[i][j] = 0.f;
        const float* qr0 = &Qs[(ty +  0) * QS_STRIDE];
        const float* qr1 = &Qs[(ty + 16) * QS_STRIDE];
        const float* qr2 = &Qs[(ty + 32) * QS_STRIDE];
        const float* qr3 = &Qs[(ty + 48) * QS_STRIDE];
        const float* kr0 = &Ks[(tx +  0) * KS_STRIDE];
        const float* kr1 = &Ks[(tx + 16) * KS_STRIDE];
        const float* kr2 = &Ks[(tx + 32) * KS_STRIDE];
        const float* kr3 = &Ks[(tx + 48) * KS_STRIDE];
        #pragma unroll 4
        for (int d = 0; d < 128; d++) {
            float a0 = qr0[d], a1 = qr1[d], a2 = qr2[d], a3 = qr3[d];
            float b0 = kr0[d], b1 = kr1[d], b2 = kr2[d], b3 = kr3[d];
            s[0][0] += a0 * b0; s[0][1] += a0 * b1; s[0][2] += a0 * b2; s[0][3] += a0 * b3;
            s[1][0] += a1 * b0; s[1][1] += a1 * b1; s[1][2] += a1 * b2; s[1][3] += a1 * b3;
            s[2][0] += a2 * b0; s[2][1] += a2 * b1; s[2][2] += a2 * b2; s[2][3] += a2 * b3;
            s[3][0] += a3 * b0; s[3][1] += a3 * b1; s[3][2] += a3 * b2; s[3][3] += a3 * b3;
        }
        bool diag = (kt == qt);
        #pragma unroll
        for (int i = 0; i < 4; i++) {
            int qi = ty + 16 * i;
            #pragma unroll
            for (int j = 0; j < 4; j++) {
                int ki = tx + 16 * j;
                float val = s[i][j] * scale;
                if (diag && ki > qi) val = -1e30f;
                Ps[qi * PS_STRIDE + ki] = val;
            }
        }
        __syncthreads();

        {
            int q = tid >> 2;
            int cc = (tid & 3) * 16;
            float* pr = &Ps[q * PS_STRIDE + cc];
            float mx = -1e30f;
            #pragma unroll
            for (int c = 0; c < 16; c++) mx = fmaxf(mx, pr[c]);
            mx = fmaxf(mx, __shfl_xor_sync(0xffffffffu, mx, 1));
            mx = fmaxf(mx, __shfl_xor_sync(0xffffffffu, mx, 2));
            float m_new = fmaxf(m_r, mx);
            float al = __expf(m_r - m_new);
            float sum = 0.f;
            #pragma unroll
            for (int c = 0; c < 16; c++) {
                float p = __expf(pr[c] - m_new);
                pr[c] = p;
                sum += p;
            }
            sum += __shfl_xor_sync(0xffffffffu, sum, 1);
            sum += __shfl_xor_sync(0xffffffffu, sum, 2);
            l_r = l_r * al + sum;
            m_r = m_new;
            if ((tid & 3) == 0) { alpha_sh[q] = al; l_sh[q] = l_r; }
        }
        __syncthreads();

        float av[4];
        #pragma unroll
        for (int i = 0; i < 4; i++) av[i] = alpha_sh[ty + 16 * i];
        #pragma unroll
        for (int i = 0; i < 4; i++)
            #pragma unroll
            for (int j = 0; j < 8; j++) o[i][j] *= av[i];

        #pragma unroll 2
        for (int k = 0; k < 64; k++) {
            float p0 = Ps[(ty +  0) * PS_STRIDE + k];
            float p1 = Ps[(ty + 16) * PS_STRIDE + k];
            float p2 = Ps[(ty + 32) * PS_STRIDE + k];
            float p3 = Ps[(ty + 48) * PS_STRIDE + k];
            float4 v0 = *(float4*)&Vs[k * VS_STRIDE + tx * 8];
            float4 v1 = *(float4*)&Vs[k * VS_STRIDE + tx * 8 + 4];
            o[0][0] += p0 * v0.x; o[0][1] += p0 * v0.y; o[0][2] += p0 * v0.z; o[0][3] += p0 * v0.w;
            o[0][4] += p0 * v1.x; o[0][5] += p0 * v1.y; o[0][6] += p0 * v1.z; o[0][7] += p0 * v1.w;
            o[1][0] += p1 * v0.x; o[1][1] += p1 * v0.y; o[1][2] += p1 * v0.z; o[1][3] += p1 * v0.w;
            o[1][4] += p1 * v1.x; o[1][5] += p1 * v1.y; o[1][6] += p1 * v1.z; o[1][7] += p1 * v1.w;
            o[2][0] += p2 * v0.x; o[2][1] += p2 * v0.y; o[2][2] += p2 * v0.z; o[2][3] += p2 * v0.w;
            o[2][4] += p2 * v1.x; o[2][5] += p2 * v1.y; o[2][6] += p2 * v1.z; o[2][7] += p2 * v1.w;
            o[3][0] += p3 * v0.x; o[3][1] += p3 * v0.y; o[3][2] += p3 * v0.z; o[3][3] += p3 * v0.w;
            o[3][4] += p3 * v1.x; o[3][5] += p3 * v1.y; o[3][6] += p3 * v1.z; o[3][7] += p3 * v1.w;
        }
    }

    #pragma unroll
    for (int i = 0; i < 4; i++) {
        int qi = ty + 16 * i;
        float inv = 1.f / l_sh[qi];
        long long off = ((long long)(b * S_LEN + q0 + qi)) * E_DIM + h * D_HEAD + tx * 8;
        #pragma unroll
        for (int jp = 0; jp < 4; jp++) {
            float v0 = o[i][jp * 2] * inv;
            float v1 = o[i][jp * 2 + 1] * inv;
            __half h0 = __float2half_rn(v0), h1 = __float2half_rn(v1);
            __half l0 = __float2half_rn(v0 - __half2float(h0));
            __half l1 = __float2half_rn(v1 - __half2float(h1));
            *(half2*)&ohi[off + jp * 2] = __halves2half2(h0, h1);
            *(half2*)&olo[off + jp * 2] = __halves2half2(l0, l1);
        }
    }
}

// ===========================================================================
extern "C" void kernel_launch(void* const* d_in, const int* in_sizes, int n_in,
                              void* d_out, int out_size)
{
    const float* hidden   = (const float*)d_in[0];
    const float* qkv_w    = (const float*)d_in[1];
    const float* o_w      = (const float*)d_in[2];
    const float* cosv     = (const float*)d_in[3];
    const float* sinv     = (const float*)d_in[4];
    const int*   blk_tab  = (const int*)d_in[7];

    float* out   = (float*)d_out;
    float* out_k = out + (size_t)T_TOK * E_DIM;
    float* out_v = out_k + (size_t)T_TOK * E_DIM;

    float*  qkv;  cudaGetSymbolAddress((void**)&qkv,  g_qkv);
    __half* wth;  cudaGetSymbolAddress((void**)&wth,  g_wt_hi);
    __half* wtl;  cudaGetSymbolAddress((void**)&wtl,  g_wt_lo);
    __half* ahi;  cudaGetSymbolAddress((void**)&ahi,  g_ahi);
    __half* alo;  cudaGetSymbolAddress((void**)&alo,  g_alo);

    // 0a) Transpose + split weights
    transpose_split_kernel<<<dim3(E_DIM / 32, E_DIM / 32, 4), dim3(32, 8)>>>(qkv_w, o_w, wth, wtl);
    // 0b) Split hidden activations
    {
        long long total = (long long)T_TOK * E_DIM / 4;
        split_a_kernel<<<(unsigned)((total + 255) / 256), 256>>>(hidden, ahi, alo);
    }

    // 1) QKV projection (fp16 split mma)
    cudaFuncSetAttribute(gemm_mma_kernel, cudaFuncAttributeMaxDynamicSharedMemorySize, GEMM_SMEM);
    gemm_mma_kernel<<<dim3(E_DIM / 128, T_TOK / 128, 3), 256, GEMM_SMEM>>>(
        ahi, alo, wth, wtl, qkv, (long long)E_DIM * E_DIM, (long long)T_TOK * E_DIM);

    // 2) RoPE on q and k
    {
        long long total = 2LL * T_TOK * H_NUM * 64;
        rope_kernel<<<(unsigned)((total + 255) / 256), 256>>>(qkv, cosv, sinv);
    }

    // 3) KV cache scatter
    {
        long long total = (long long)B_SZ * NB_BLK * H_NUM * BS_BLK * D_HEAD;
        cache_write_kernel<<<(unsigned)((total + 255) / 256), 256>>>(qkv, blk_tab, out_k, out_v);
    }

    // 4) Flash attention (fp32 compute, hi/lo half output)
    {
        int smem = (64 * QS_STRIDE + 64 * KS_STRIDE + 64 * VS_STRIDE +
                    64 * PS_STRIDE + 64 + 64) * (int)sizeof(float);
        cudaFuncSetAttribute(attn_kernel, cudaFuncAttributeMaxDynamicSharedMemorySize, smem);
        attn_kernel<<<dim3(S_LEN / 64, H_NUM, B_SZ), 256, smem>>>(qkv, ahi, alo);
    }

    // 5) Output projection (fp16 split mma)
    gemm_mma_kernel<<<dim3(E_DIM / 128, T_TOK / 128, 1), 256, GEMM_SMEM>>>(
        ahi, alo, wth + 3ULL * E_DIM * E_DIM, wtl + 3ULL * E_DIM * E_DIM, out, 0, 0);
}

// round 9
// speedup vs baseline: 2.1555x; 1.2113x over previous
#include <cuda_runtime.h>
#include <cuda_fp16.h>
#include <cstdint>

#define T_TOK 4096
#define E_DIM 4096
#define B_SZ  4
#define S_LEN 1024
#define H_NUM 32
#define D_HEAD 128
#define BS_BLK 16
#define NB_BLK 64

// Scratch (allocation-free rule: __device__ globals)
__device__ float  g_qkv[3ULL * T_TOK * E_DIM];        // q | k | v, each [T, E] fp32
__device__ __half g_wt_hi[4ULL * E_DIM * E_DIM];      // transposed weight hi planes [4][N][K]
__device__ __half g_wt_lo[4ULL * E_DIM * E_DIM];      // transposed weight lo planes
__device__ __half g_ahi[(size_t)T_TOK * E_DIM];       // activation hi plane [T, E]
__device__ __half g_alo[(size_t)T_TOK * E_DIM];       // activation lo plane

// ===========================================================================
// helpers
// ===========================================================================
__device__ __forceinline__ uint32_t smem_u32(const void* p) {
    uint32_t a;
    asm("{ .reg .u64 t; cvta.to.shared.u64 t, %1; cvt.u32.u64 %0, t; }" : "=r"(a) : "l"(p));
    return a;
}
__device__ __forceinline__ void cp16(uint32_t dst, const void* src) {
    asm volatile("cp.async.ca.shared.global [%0], [%1], 16;" :: "r"(dst), "l"(src));
}
#define CP_COMMIT() asm volatile("cp.async.commit_group;" ::: "memory")
#define CP_WAIT2()  asm volatile("cp.async.wait_group 2;" ::: "memory")

__device__ __forceinline__ void mma_f16(float* c, const uint32_t* a, const uint32_t* b) {
    asm volatile(
        "mma.sync.aligned.m16n8k16.row.col.f32.f16.f16.f32 "
        "{%0,%1,%2,%3}, {%4,%5,%6,%7}, {%8,%9}, {%0,%1,%2,%3};"
        : "+f"(c[0]), "+f"(c[1]), "+f"(c[2]), "+f"(c[3])
        : "r"(a[0]), "r"(a[1]), "r"(a[2]), "r"(a[3]), "r"(b[0]), "r"(b[1]));
}
__device__ __forceinline__ void ldmatrix_x4(uint32_t* r, uint32_t addr) {
    asm volatile("ldmatrix.sync.aligned.m8n8.x4.shared.b16 {%0,%1,%2,%3}, [%4];"
                 : "=r"(r[0]), "=r"(r[1]), "=r"(r[2]), "=r"(r[3]) : "r"(addr));
}

// ===========================================================================
// Weight transpose + hi/lo split: W[z][k][n] fp32 -> Wt_hi/lo[z][n][k] half
// ===========================================================================
__global__ void transpose_split_kernel(const float* __restrict__ qkv_w,
                                       const float* __restrict__ o_w,
                                       __half* __restrict__ out_hi,
                                       __half* __restrict__ out_lo)
{
    __shared__ float tile[32][33];
    int z = blockIdx.z;
    const float* src = (z < 3) ? qkv_w + (size_t)z * E_DIM * E_DIM : o_w;
    __half* dhi = out_hi + (size_t)z * E_DIM * E_DIM;
    __half* dlo = out_lo + (size_t)z * E_DIM * E_DIM;
    int k0 = blockIdx.y * 32, n0 = blockIdx.x * 32;
    int tx = threadIdx.x, ty = threadIdx.y;
    #pragma unroll
    for (int j = 0; j < 32; j += 8)
        tile[ty + j][tx] = src[(size_t)(k0 + ty + j) * E_DIM + n0 + tx];
    __syncthreads();
    #pragma unroll
    for (int j = 0; j < 32; j += 8) {
        float x = tile[tx][ty + j];
        __half hi = __float2half_rn(x);
        __half lo = __float2half_rn(x - __half2float(hi));
        size_t off = (size_t)(n0 + ty + j) * E_DIM + k0 + tx;
        dhi[off] = hi;
        dlo[off] = lo;
    }
}

// ===========================================================================
// Activation hi/lo split: X[T,E] fp32 -> hi/lo half planes
// ===========================================================================
__global__ void split_a_kernel(const float* __restrict__ x,
                               __half* __restrict__ xhi, __half* __restrict__ xlo)
{
    long long i = ((long long)blockIdx.x * blockDim.x + threadIdx.x) * 4;
    if (i >= (long long)T_TOK * E_DIM) return;
    float4 v = *(const float4*)&x[i];
    __half h0 = __float2half_rn(v.x), h1 = __float2half_rn(v.y);
    __half h2 = __float2half_rn(v.z), h3 = __float2half_rn(v.w);
    __half l0 = __float2half_rn(v.x - __half2float(h0));
    __half l1 = __float2half_rn(v.y - __half2float(h1));
    __half l2 = __float2half_rn(v.z - __half2float(h2));
    __half l3 = __float2half_rn(v.w - __half2float(h3));
    *(half2*)&xhi[i]     = __halves2half2(h0, h1);
    *(half2*)&xhi[i + 2] = __halves2half2(h2, h3);
    *(half2*)&xlo[i]     = __halves2half2(l0, l1);
    *(half2*)&xlo[i + 2] = __halves2half2(l2, l3);
}

// ===========================================================================
// fp16 hi/lo split GEMM with ldmatrix: C[z] = A @ Bt[z]   (fp32 out)
// Block tile 128x128, K-tile 16, 8 warps (2Mx4N), warp tile 64x32.
// Row layout per stage: 128 rows x 80B  (hi 32B | lo 32B | 16B pad) per matrix.
// 4-stage cp.async pipeline, ONE barrier per kt.
// ===========================================================================
#define KT 16
#define NK_ITERS (E_DIM / KT)              // 256
#define ROW_B 80                           // bytes per row
#define TILE_B (128 * ROW_B)               // 10240 per matrix per stage
#define STAGE_B (2 * TILE_B)               // 20480
#define NSTAGES 4
#define GEMM_SMEM (NSTAGES * STAGE_B)      // 81920

__device__ __forceinline__ void stage_load(uint32_t smb, int st,
                                           const __half* __restrict__ Ahi,
                                           const __half* __restrict__ Alo,
                                           const __half* __restrict__ Bhi,
                                           const __half* __restrict__ Blo,
                                           int k0, int tid)
{
    #pragma unroll
    for (int j = 0; j < 4; ++j) {
        int idx = tid + 256 * j;
        int m   = idx >> 9;
        int r   = (idx >> 2) & 127;
        int seg = idx & 3;                 // 0,1 = hi halves ; 2,3 = lo halves
        uint32_t dst = smb + st * STAGE_B + m * TILE_B + r * ROW_B + seg * 16;
        const __half* hp = m ? Bhi : Ahi;
        const __half* lp = m ? Blo : Alo;
        const __half* src = (seg < 2 ? hp : lp) + (long long)r * E_DIM + k0 + (seg & 1) * 8;
        cp16(dst, src);
    }
}

__global__ __launch_bounds__(256, 1)
void gemm_mma_kernel(const __half* __restrict__ Ahi, const __half* __restrict__ Alo,
                     const __half* __restrict__ Bhi, const __half* __restrict__ Blo,
                     float* __restrict__ C, long long strideB, long long strideC)
{
    extern __shared__ char sm[];
    uint32_t smb = smem_u32(sm);
    const int tid = threadIdx.x;
    const int wid = tid >> 5;
    const int lane = tid & 31;
    const int grp = lane >> 2;       // 0..7
    const int thr = lane & 3;        // 0..3
    const int warp_m = wid >> 2;     // 0..1
    const int warp_n = wid & 3;      // 0..3

    const int m0 = blockIdx.y * 128;
    const int n0 = blockIdx.x * 128;
    const __half* Ah = Ahi + (long long)m0 * E_DIM;
    const __half* Al = Alo + (long long)m0 * E_DIM;
    const __half* Bh = Bhi + (long long)blockIdx.z * strideB + (long long)n0 * E_DIM;
    const __half* Bl = Blo + (long long)blockIdx.z * strideB + (long long)n0 * E_DIM;
    float* Cg = C + (long long)blockIdx.z * strideC;

    float acc[4][4][4];
    #pragma unroll
    for (int mi = 0; mi < 4; mi++)
        #pragma unroll
        for (int ni = 0; ni < 4; ni++)
            #pragma unroll
            for (int q = 0; q < 4; q++) acc[mi][ni][q] = 0.f;

    // ldmatrix lane addresses (within current stage's A / B tiles)
    // A (x4): lane l -> row base + (l & 15), byte offset (l >> 4) * 16
    const uint32_t a_lane_off =
        (uint32_t)((warp_m * 64 + (lane & 15)) * ROW_B + (lane >> 4) * 16);
    // B (x4, two n-groups of 8): lane l -> row base + (l>>4)*8 + (l&7),
    //                            byte offset ((l>>3)&1) * 16
    const uint32_t b_lane_off =
        (uint32_t)((warp_n * 32 + (lane >> 4) * 8 + (lane & 7)) * ROW_B + ((lane >> 3) & 1) * 16);

    // prologue: stages 0,1,2
    stage_load(smb, 0, Ah, Al, Bh, Bl, 0, tid);       CP_COMMIT();
    stage_load(smb, 1, Ah, Al, Bh, Bl, KT, tid);      CP_COMMIT();
    stage_load(smb, 2, Ah, Al, Bh, Bl, 2 * KT, tid);  CP_COMMIT();

    for (int kt = 0; kt < NK_ITERS; ++kt) {
        int st = kt & 3;
        CP_WAIT2();
        __syncthreads();   // stage st ready; stage (kt+3)&3 free (read at kt-1)

        if (kt + 3 < NK_ITERS) {
            stage_load(smb, (kt + 3) & 3, Ah, Al, Bh, Bl, (kt + 3) * KT, tid);
        }
        CP_COMMIT();

        uint32_t abase = smb + st * STAGE_B + a_lane_off;
        uint32_t bbase = smb + st * STAGE_B + TILE_B + b_lane_off;

        uint32_t ah[4][4], al[4][4], bfrag_h[2][4], bfrag_l[2][4];
        #pragma unroll
        for (int mi = 0; mi < 4; mi++) {
            ldmatrix_x4(ah[mi], abase + mi * 16 * ROW_B);        // hi (bytes 0..31)
            ldmatrix_x4(al[mi], abase + mi * 16 * ROW_B + 32);   // lo (bytes 32..63)
        }
        #pragma unroll
        for (int g = 0; g < 2; g++) {
            ldmatrix_x4(bfrag_h[g], bbase + g * 16 * ROW_B);
            ldmatrix_x4(bfrag_l[g], bbase + g * 16 * ROW_B + 32);
        }
        // bfrag[g] = {b(n8g+0..7, k0-7), b(.., k8-15), b(n8g+8..15, k0-7), b(.., k8-15)}
        #pragma unroll
        for (int mi = 0; mi < 4; mi++)
            #pragma unroll
            for (int ni = 0; ni < 4; ni++) {
                const uint32_t* bh = &bfrag_h[ni >> 1][(ni & 1) * 2];
                const uint32_t* bl = &bfrag_l[ni >> 1][(ni & 1) * 2];
                mma_f16(acc[mi][ni], al[mi], bh);
                mma_f16(acc[mi][ni], ah[mi], bl);
                mma_f16(acc[mi][ni], ah[mi], bh);
            }
        // no trailing barrier: next iteration's leading barrier protects reuse
    }

    // epilogue: direct global stores
    #pragma unroll
    for (int mi = 0; mi < 4; mi++) {
        long long r0 = m0 + warp_m * 64 + mi * 16 + grp;
        #pragma unroll
        for (int ni = 0; ni < 4; ni++) {
            long long col = n0 + warp_n * 32 + ni * 8 + thr * 2;
            *(float2*)&Cg[r0 * E_DIM + col]       = make_float2(acc[mi][ni][0], acc[mi][ni][1]);
            *(float2*)&Cg[(r0 + 8) * E_DIM + col] = make_float2(acc[mi][ni][2], acc[mi][ni][3]);
        }
    }
}

// ===========================================================================
// RoPE (in-place on q and k slices of g_qkv)
// ===========================================================================
__global__ void rope_kernel(float* __restrict__ qkv,
                            const float* __restrict__ cosv,
                            const float* __restrict__ sinv)
{
    long long idx = (long long)blockIdx.x * blockDim.x + threadIdx.x;
    if (idx >= 2LL * T_TOK * H_NUM * 64) return;
    int j = idx & 63;
    int h = (idx >> 6) & (H_NUM - 1);
    long long t = (idx >> 11) & (T_TOK - 1);
    int which = (int)(idx >> 23);   // 0 = q, 1 = k
    float* base = qkv + (long long)which * T_TOK * E_DIM + t * E_DIM + h * D_HEAD;
    float c = cosv[t * 64 + j];
    float s = sinv[t * 64 + j];
    float x1 = base[j];
    float x2 = base[j + 64];
    base[j]      = x1 * c - x2 * s;
    base[j + 64] = x2 * c + x1 * s;
}

// ===========================================================================
// KV cache scatter
// ===========================================================================
__global__ void cache_write_kernel(const float* __restrict__ qkv,
                                   const int* __restrict__ block_tables,
                                   float* __restrict__ out_k,
                                   float* __restrict__ out_v)
{
    long long idx = (long long)blockIdx.x * blockDim.x + threadIdx.x;
    if (idx >= (long long)B_SZ * NB_BLK * H_NUM * BS_BLK * D_HEAD) return;
    int d  = idx & 127;
    int bs = (idx >> 7) & (BS_BLK - 1);
    int h  = (idx >> 11) & (H_NUM - 1);
    long long nbb = idx >> 16;
    int b  = (int)(nbb >> 6);
    int nb = (int)(nbb & 63);
    int blk = block_tables[b * NB_BLK + nb];
    long long t = (long long)b * S_LEN + nb * BS_BLK + bs;
    long long src = t * E_DIM + h * D_HEAD + d;
    long long dst = (((long long)blk * H_NUM + h) * BS_BLK + bs) * D_HEAD + d;
    out_k[dst] = qkv[(long long)T_TOK * E_DIM + src];
    out_v[dst] = qkv[2LL * T_TOK * E_DIM + src];
}

// ===========================================================================
// Flash attention, fp32, causal. Writes hi/lo half planes for the O-proj GEMM.
// ===========================================================================
#define QS_STRIDE 129
#define KS_STRIDE 129
#define VS_STRIDE 132
#define PS_STRIDE 65

__global__ __launch_bounds__(256, 1)
void attn_kernel(const float* __restrict__ qkv,
                 __half* __restrict__ ohi, __half* __restrict__ olo)
{
    extern __shared__ float smf[];
    float* Qs = smf;
    float* Ks = Qs + 64 * QS_STRIDE;
    float* Vs = Ks + 64 * KS_STRIDE;
    float* Ps = Vs + 64 * VS_STRIDE;
    float* alpha_sh = Ps + 64 * PS_STRIDE;
    float* l_sh = alpha_sh + 64;

    int tid = threadIdx.x;
    int tx = tid & 15, ty = tid >> 4;
    int qt = blockIdx.x, h = blockIdx.y, b = blockIdx.z;
    int q0 = qt * 64;

    const long long TE = (long long)T_TOK * E_DIM;
    const float* qbase = qkv;
    const float* kbase = qkv + TE;
    const float* vbase = qkv + 2 * TE;
    const float scale = 0.08838834764831845f;

    for (int c = tid; c < 64 * 32; c += 256) {
        int row = c >> 5;
        int c4 = (c & 31) * 4;
        float4 v = *(const float4*)&qbase[((long long)(b * S_LEN + q0 + row)) * E_DIM + h * D_HEAD + c4];
        Qs[row * QS_STRIDE + c4]     = v.x;
        Qs[row * QS_STRIDE + c4 + 1] = v.y;
        Qs[row * QS_STRIDE + c4 + 2] = v.z;
        Qs[row * QS_STRIDE + c4 + 3] = v.w;
    }

    float m_r = -1e30f, l_r = 0.f;
    float o[4][8];
    #pragma unroll
    for (int i = 0; i < 4; i++)
        #pragma unroll
        for (int j = 0; j < 8; j++) o[i][j] = 0.f;

    int nkt = qt + 1;
    for (int kt = 0; kt < nkt; kt++) {
        int k0 = kt * 64;
        __syncthreads();
        for (int c = tid; c < 64 * 32; c += 256) {
            int row = c >> 5;
            int c4 = (c & 31) * 4;
            long long goff = ((long long)(b * S_LEN + k0 + row)) * E_DIM + h * D_HEAD + c4;
            float4 kv = *(const float4*)&kbase[goff];
            Ks[row * KS_STRIDE + c4]     = kv.x;
            Ks[row * KS_STRIDE + c4 + 1] = kv.y;
            Ks[row * KS_STRIDE + c4 + 2] = kv.z;
            Ks[row * KS_STRIDE + c4 + 3] = kv.w;
            float4 vv = *(const float4*)&vbase[goff];
            *(float4*)&Vs[row * VS_STRIDE + c4] = vv;
        }
        __syncthreads();

        float s[4][4];
        #pragma unroll
        for (int i = 0; i < 4; i++)
            #pragma unroll
            for (int j = 0; j < 4; j++) s[i][j] = 0.f;
        const float* qr0 = &Qs[(ty +  0) * QS_STRIDE];
        const float* qr1 = &Qs[(ty + 16) * QS_STRIDE];
        const float* qr2 = &Qs[(ty + 32) * QS_STRIDE];
        const float* qr3 = &Qs[(ty + 48) * QS_STRIDE];
        const float* kr0 = &Ks[(tx +  0) * KS_STRIDE];
        const float* kr1 = &Ks[(tx + 16) * KS_STRIDE];
        const float* kr2 = &Ks[(tx + 32) * KS_STRIDE];
        const float* kr3 = &Ks[(tx + 48) * KS_STRIDE];
        #pragma unroll 4
        for (int d = 0; d < 128; d++) {
            float a0 = qr0[d], a1 = qr1[d], a2 = qr2[d], a3 = qr3[d];
            float b0 = kr0[d], b1 = kr1[d], b2 = kr2[d], b3 = kr3[d];
            s[0][0] += a0 * b0; s[0][1] += a0 * b1; s[0][2] += a0 * b2; s[0][3] += a0 * b3;
            s[1][0] += a1 * b0; s[1][1] += a1 * b1; s[1][2] += a1 * b2; s[1][3] += a1 * b3;
            s[2][0] += a2 * b0; s[2][1] += a2 * b1; s[2][2] += a2 * b2; s[2][3] += a2 * b3;
            s[3][0] += a3 * b0; s[3][1] += a3 * b1; s[3][2] += a3 * b2; s[3][3] += a3 * b3;
        }
        bool diag = (kt == qt);
        #pragma unroll
        for (int i = 0; i < 4; i++) {
            int qi = ty + 16 * i;
            #pragma unroll
            for (int j = 0; j < 4; j++) {
                int ki = tx + 16 * j;
                float val = s[i][j] * scale;
                if (diag && ki > qi) val = -1e30f;
                Ps[qi * PS_STRIDE + ki] = val;
            }
        }
        __syncthreads();

        {
            int q = tid >> 2;
            int cc = (tid & 3) * 16;
            float* pr = &Ps[q * PS_STRIDE + cc];
            float mx = -1e30f;
            #pragma unroll
            for (int c = 0; c < 16; c++) mx = fmaxf(mx, pr[c]);
            mx = fmaxf(mx, __shfl_xor_sync(0xffffffffu, mx, 1));
            mx = fmaxf(mx, __shfl_xor_sync(0xffffffffu, mx, 2));
            float m_new = fmaxf(m_r, mx);
            float al = __expf(m_r - m_new);
            float sum = 0.f;
            #pragma unroll
            for (int c = 0; c < 16; c++) {
                float p = __expf(pr[c] - m_new);
                pr[c] = p;
                sum += p;
            }
            sum += __shfl_xor_sync(0xffffffffu, sum, 1);
            sum += __shfl_xor_sync(0xffffffffu, sum, 2);
            l_r = l_r * al + sum;
            m_r = m_new;
            if ((tid & 3) == 0) { alpha_sh[q] = al; l_sh[q] = l_r; }
        }
        __syncthreads();

        float av[4];
        #pragma unroll
        for (int i = 0; i < 4; i++) av[i] = alpha_sh[ty + 16 * i];
        #pragma unroll
        for (int i = 0; i < 4; i++)
            #pragma unroll
            for (int j = 0; j < 8; j++) o[i][j] *= av[i];

        #pragma unroll 2
        for (int k = 0; k < 64; k++) {
            float p0 = Ps[(ty +  0) * PS_STRIDE + k];
            float p1 = Ps[(ty + 16) * PS_STRIDE + k];
            float p2 = Ps[(ty + 32) * PS_STRIDE + k];
            float p3 = Ps[(ty + 48) * PS_STRIDE + k];
            float4 v0 = *(float4*)&Vs[k * VS_STRIDE + tx * 8];
            float4 v1 = *(float4*)&Vs[k * VS_STRIDE + tx * 8 + 4];
            o[0][0] += p0 * v0.x; o[0][1] += p0 * v0.y; o[0][2] += p0 * v0.z; o[0][3] += p0 * v0.w;
            o[0][4] += p0 * v1.x; o[0][5] += p0 * v1.y; o[0][6] += p0 * v1.z; o[0][7] += p0 * v1.w;
            o[1][0] += p1 * v0.x; o[1][1] += p1 * v0.y; o[1][2] += p1 * v0.z; o[1][3] += p1 * v0.w;
            o[1][4] += p1 * v1.x; o[1][5] += p1 * v1.y; o[1][6] += p1 * v1.z; o[1][7] += p1 * v1.w;
            o[2][0] += p2 * v0.x; o[2][1] += p2 * v0.y; o[2][2] += p2 * v0.z; o[2][3] += p2 * v0.w;
            o[2][4] += p2 * v1.x; o[2][5] += p2 * v1.y; o[2][6] += p2 * v1.z; o[2][7] += p2 * v1.w;
            o[3][0] += p3 * v0.x; o[3][1] += p3 * v0.y; o[3][2] += p3 * v0.z; o[3][3] += p3 * v0.w;
            o[3][4] += p3 * v1.x; o[3][5] += p3 * v1.y; o[3][6] += p3 * v1.z; o[3][7] += p3 * v1.w;
        }
    }

    #pragma unroll
    for (int i = 0; i < 4; i++) {
        int qi = ty + 16 * i;
        float inv = 1.f / l_sh[qi];
        long long off = ((long long)(b * S_LEN + q0 + qi)) * E_DIM + h * D_HEAD + tx * 8;
        #pragma unroll
        for (int jp = 0; jp < 4; jp++) {
            float v0 = o[i][jp * 2] * inv;
            float v1 = o[i][jp * 2 + 1] * inv;
            __half h0 = __float2half_rn(v0), h1 = __float2half_rn(v1);
            __half l0 = __float2half_rn(v0 - __half2float(h0));
            __half l1 = __float2half_rn(v1 - __half2float(h1));
            *(half2*)&ohi[off + jp * 2] = __halves2half2(h0, h1);
            *(half2*)&olo[off + jp * 2] = __halves2half2(l0, l1);
        }
    }
}

// ===========================================================================
extern "C" void kernel_launch(void* const* d_in, const int* in_sizes, int n_in,
                              void* d_out, int out_size)
{
    const float* hidden   = (const float*)d_in[0];
    const float* qkv_w    = (const float*)d_in[1];
    const float* o_w      = (const float*)d_in[2];
    const float* cosv     = (const float*)d_in[3];
    const float* sinv     = (const float*)d_in[4];
    const int*   blk_tab  = (const int*)d_in[7];

    float* out   = (float*)d_out;
    float* out_k = out + (size_t)T_TOK * E_DIM;
    float* out_v = out_k + (size_t)T_TOK * E_DIM;

    float*  qkv;  cudaGetSymbolAddress((void**)&qkv,  g_qkv);
    __half* wth;  cudaGetSymbolAddress((void**)&wth,  g_wt_hi);
    __half* wtl;  cudaGetSymbolAddress((void**)&wtl,  g_wt_lo);
    __half* ahi;  cudaGetSymbolAddress((void**)&ahi,  g_ahi);
    __half* alo;  cudaGetSymbolAddress((void**)&alo,  g_alo);

    // 0a) Transpose + split weights
    transpose_split_kernel<<<dim3(E_DIM / 32, E_DIM / 32, 4), dim3(32, 8)>>>(qkv_w, o_w, wth, wtl);
    // 0b) Split hidden activations
    {
        long long total = (long long)T_TOK * E_DIM / 4;
        split_a_kernel<<<(unsigned)((total + 255) / 256), 256>>>(hidden, ahi, alo);
    }

    // 1) QKV projection (fp16 split mma + ldmatrix)
    cudaFuncSetAttribute(gemm_mma_kernel, cudaFuncAttributeMaxDynamicSharedMemorySize, GEMM_SMEM);
    gemm_mma_kernel<<<dim3(E_DIM / 128, T_TOK / 128, 3), 256, GEMM_SMEM>>>(
        ahi, alo, wth, wtl, qkv, (long long)E_DIM * E_DIM, (long long)T_TOK * E_DIM);

    // 2) RoPE on q and k
    {
        long long total = 2LL * T_TOK * H_NUM * 64;
        rope_kernel<<<(unsigned)((total + 255) / 256), 256>>>(qkv, cosv, sinv);
    }

    // 3) KV cache scatter
    {
        long long total = (long long)B_SZ * NB_BLK * H_NUM * BS_BLK * D_HEAD;
        cache_write_kernel<<<(unsigned)((total + 255) / 256), 256>>>(qkv, blk_tab, out_k, out_v);
    }

    // 4) Flash attention (fp32 compute, hi/lo half output)
    {
        int smem = (64 * QS_STRIDE + 64 * KS_STRIDE + 64 * VS_STRIDE +
                    64 * PS_STRIDE + 64 + 64) * (int)sizeof(float);
        cudaFuncSetAttribute(attn_kernel, cudaFuncAttributeMaxDynamicSharedMemorySize, smem);
        attn_kernel<<<dim3(S_LEN / 64, H_NUM, B_SZ), 256, smem>>>(qkv, ahi, alo);
    }

    // 5) Output projection (fp16 split mma + ldmatrix)
    gemm_mma_kernel<<<dim3(E_DIM / 128, T_TOK / 128, 1), 256, GEMM_SMEM>>>(
        ahi, alo, wth + 3ULL * E_DIM * E_DIM, wtl + 3ULL * E_DIM * E_DIM, out, 0, 0);
}

// round 12
// speedup vs baseline: 2.3342x; 1.0829x over previous
#include <cuda_runtime.h>
#include <cuda_fp16.h>
#include <cstdint>

#define T_TOK 4096
#define E_DIM 4096
#define B_SZ  4
#define S_LEN 1024
#define H_NUM 32
#define D_HEAD 128
#define BS_BLK 16
#define NB_BLK 64

// Scratch (allocation-free rule: __device__ globals)
__device__ float  g_qkv[3ULL * T_TOK * E_DIM];        // q | k | v, each [T, E] fp32
__device__ __half g_wt_hi[4ULL * E_DIM * E_DIM];      // transposed weight hi planes [4][N][K]
__device__ __half g_wt_lo[4ULL * E_DIM * E_DIM];      // transposed weight lo planes
__device__ __half g_ahi[(size_t)T_TOK * E_DIM];       // activation hi plane [T, E]
__device__ __half g_alo[(size_t)T_TOK * E_DIM];       // activation lo plane

// ===========================================================================
// helpers
// ===========================================================================
__device__ __forceinline__ uint32_t smem_u32(const void* p) {
    uint32_t a;
    asm("{ .reg .u64 t; cvta.to.shared.u64 t, %1; cvt.u32.u64 %0, t; }" : "=r"(a) : "l"(p));
    return a;
}
__device__ __forceinline__ void cp16(uint32_t dst, const void* src) {
    asm volatile("cp.async.ca.shared.global [%0], [%1], 16;" :: "r"(dst), "l"(src));
}
#define CP_COMMIT() asm volatile("cp.async.commit_group;" ::: "memory")
#define CP_WAIT0()  asm volatile("cp.async.wait_group 0;" ::: "memory")

__device__ __forceinline__ void mma_f16(float* c, const uint32_t* a, const uint32_t* b) {
    asm volatile(
        "mma.sync.aligned.m16n8k16.row.col.f32.f16.f16.f32 "
        "{%0,%1,%2,%3}, {%4,%5,%6,%7}, {%8,%9}, {%0,%1,%2,%3};"
        : "+f"(c[0]), "+f"(c[1]), "+f"(c[2]), "+f"(c[3])
        : "r"(a[0]), "r"(a[1]), "r"(a[2]), "r"(a[3]), "r"(b[0]), "r"(b[1]));
}
__device__ __forceinline__ void ldmatrix_x4(uint32_t* r, uint32_t addr) {
    asm volatile("ldmatrix.sync.aligned.m8n8.x4.shared.b16 {%0,%1,%2,%3}, [%4];"
                 : "=r"(r[0]), "=r"(r[1]), "=r"(r[2]), "=r"(r[3]) : "r"(addr));
}

// ===========================================================================
// Weight transpose + hi/lo split: W[z][k][n] fp32 -> Wt_hi/lo[z][n][k] half
// ===========================================================================
__global__ void transpose_split_kernel(const float* __restrict__ qkv_w,
                                       const float* __restrict__ o_w,
                                       __half* __restrict__ out_hi,
                                       __half* __restrict__ out_lo)
{
    __shared__ float tile[32][33];
    int z = blockIdx.z;
    const float* src = (z < 3) ? qkv_w + (size_t)z * E_DIM * E_DIM : o_w;
    __half* dhi = out_hi + (size_t)z * E_DIM * E_DIM;
    __half* dlo = out_lo + (size_t)z * E_DIM * E_DIM;
    int k0 = blockIdx.y * 32, n0 = blockIdx.x * 32;
    int tx = threadIdx.x, ty = threadIdx.y;
    #pragma unroll
    for (int j = 0; j < 32; j += 8)
        tile[ty + j][tx] = src[(size_t)(k0 + ty + j) * E_DIM + n0 + tx];
    __syncthreads();
    #pragma unroll
    for (int j = 0; j < 32; j += 8) {
        float x = tile[tx][ty + j];
        __half hi = __float2half_rn(x);
        __half lo = __float2half_rn(x - __half2float(hi));
        size_t off = (size_t)(n0 + ty + j) * E_DIM + k0 + tx;
        dhi[off] = hi;
        dlo[off] = lo;
    }
}

// ===========================================================================
// Activation hi/lo split: X[T,E] fp32 -> hi/lo half planes
// ===========================================================================
__global__ void split_a_kernel(const float* __restrict__ x,
                               __half* __restrict__ xhi, __half* __restrict__ xlo)
{
    long long i = ((long long)blockIdx.x * blockDim.x + threadIdx.x) * 4;
    if (i >= (long long)T_TOK * E_DIM) return;
    float4 v = *(const float4*)&x[i];
    __half h0 = __float2half_rn(v.x), h1 = __float2half_rn(v.y);
    __half h2 = __float2half_rn(v.z), h3 = __float2half_rn(v.w);
    __half l0 = __float2half_rn(v.x - __half2float(h0));
    __half l1 = __float2half_rn(v.y - __half2float(h1));
    __half l2 = __float2half_rn(v.z - __half2float(h2));
    __half l3 = __float2half_rn(v.w - __half2float(h3));
    *(half2*)&xhi[i]     = __halves2half2(h0, h1);
    *(half2*)&xhi[i + 2] = __halves2half2(h2, h3);
    *(half2*)&xlo[i]     = __halves2half2(l0, l1);
    *(half2*)&xlo[i + 2] = __halves2half2(l2, l3);
}

// ===========================================================================
// fp16 hi/lo split GEMM with ldmatrix: C[z] = A @ Bt[z]   (fp32 out)
// Block tile 128x128, K-tile 16, 8 warps (2Mx4N), warp tile 64x32.
// Row layout per stage: 128 rows x 80B  (hi 32B | lo 32B | 16B pad) per matrix.
// 2-stage cp.async double buffer, wait THEN barrier (visibility), 2 CTAs/SM.
// ===========================================================================
#define KT 16
#define NK_ITERS (E_DIM / KT)              // 256
#define ROW_B 80                           // bytes per row
#define TILE_B (128 * ROW_B)               // 10240 per matrix per stage
#define STAGE_B (2 * TILE_B)               // 20480
#define NSTAGES 2
#define GEMM_SMEM (NSTAGES * STAGE_B)      // 40960

__device__ __forceinline__ void stage_load(uint32_t smb, int st,
                                           const __half* __restrict__ Ahi,
                                           const __half* __restrict__ Alo,
                                           const __half* __restrict__ Bhi,
                                           const __half* __restrict__ Blo,
                                           int k0, int tid)
{
    #pragma unroll
    for (int j = 0; j < 4; ++j) {
        int idx = tid + 256 * j;
        int m   = idx >> 9;
        int r   = (idx >> 2) & 127;
        int seg = idx & 3;                 // 0,1 = hi halves ; 2,3 = lo halves
        uint32_t dst = smb + st * STAGE_B + m * TILE_B + r * ROW_B + seg * 16;
        const __half* hp = m ? Bhi : Ahi;
        const __half* lp = m ? Blo : Alo;
        const __half* src = (seg < 2 ? hp : lp) + (long long)r * E_DIM + k0 + (seg & 1) * 8;
        cp16(dst, src);
    }
}

__global__ __launch_bounds__(256, 2)
void gemm_mma_kernel(const __half* __restrict__ Ahi, const __half* __restrict__ Alo,
                     const __half* __restrict__ Bhi, const __half* __restrict__ Blo,
                     float* __restrict__ C, long long strideB, long long strideC)
{
    extern __shared__ char sm[];
    uint32_t smb = smem_u32(sm);
    const int tid = threadIdx.x;
    const int wid = tid >> 5;
    const int lane = tid & 31;
    const int grp = lane >> 2;       // 0..7
    const int thr = lane & 3;        // 0..3
    const int warp_m = wid >> 2;     // 0..1
    const int warp_n = wid & 3;      // 0..3

    const int m0 = blockIdx.y * 128;
    const int n0 = blockIdx.x * 128;
    const __half* Ah = Ahi + (long long)m0 * E_DIM;
    const __half* Al = Alo + (long long)m0 * E_DIM;
    const __half* Bh = Bhi + (long long)blockIdx.z * strideB + (long long)n0 * E_DIM;
    const __half* Bl = Blo + (long long)blockIdx.z * strideB + (long long)n0 * E_DIM;
    float* Cg = C + (long long)blockIdx.z * strideC;

    float acc[4][4][4];
    #pragma unroll
    for (int mi = 0; mi < 4; mi++)
        #pragma unroll
        for (int ni = 0; ni < 4; ni++)
            #pragma unroll
            for (int q = 0; q < 4; q++) acc[mi][ni][q] = 0.f;

    // ldmatrix lane addresses (within current stage's A / B tiles)
    const uint32_t a_lane_off =
        (uint32_t)((warp_m * 64 + (lane & 15)) * ROW_B + (lane >> 4) * 16);
    const uint32_t b_lane_off =
        (uint32_t)((warp_n * 32 + (lane >> 4) * 8 + (lane & 7)) * ROW_B + ((lane >> 3) & 1) * 16);

    // prologue: stage 0
    stage_load(smb, 0, Ah, Al, Bh, Bl, 0, tid);
    CP_COMMIT();

    for (int kt = 0; kt < NK_ITERS; ++kt) {
        int st = kt & 1;
        CP_WAIT0();        // load(kt) complete (this thread's copies)
        __syncthreads();   // ...visible to all warps; buf^1 reads from kt-1 retired

        if (kt + 1 < NK_ITERS) {
            stage_load(smb, (kt + 1) & 1, Ah, Al, Bh, Bl, (kt + 1) * KT, tid);
            CP_COMMIT();
        }

        uint32_t abase = smb + st * STAGE_B + a_lane_off;
        uint32_t bbase = smb + st * STAGE_B + TILE_B + b_lane_off;

        uint32_t ah[4][4], al[4][4];
        #pragma unroll
        for (int mi = 0; mi < 4; mi++) {
            ldmatrix_x4(ah[mi], abase + mi * 16 * ROW_B);        // hi (bytes 0..31)
            ldmatrix_x4(al[mi], abase + mi * 16 * ROW_B + 32);   // lo (bytes 32..63)
        }
        #pragma unroll
        for (int g = 0; g < 2; g++) {
            uint32_t bh[4], bl[4];
            ldmatrix_x4(bh, bbase + g * 16 * ROW_B);
            ldmatrix_x4(bl, bbase + g * 16 * ROW_B + 32);
            #pragma unroll
            for (int mi = 0; mi < 4; mi++)
                #pragma unroll
                for (int nj = 0; nj < 2; nj++) {
                    float* accp = acc[mi][g * 2 + nj];
                    mma_f16(accp, al[mi], &bh[nj * 2]);
                    mma_f16(accp, ah[mi], &bl[nj * 2]);
                    mma_f16(accp, ah[mi], &bh[nj * 2]);
                }
        }
    }

    // epilogue: direct global stores
    #pragma unroll
    for (int mi = 0; mi < 4; mi++) {
        long long r0 = m0 + warp_m * 64 + mi * 16 + grp;
        #pragma unroll
        for (int ni = 0; ni < 4; ni++) {
            long long col = n0 + warp_n * 32 + ni * 8 + thr * 2;
            *(float2*)&Cg[r0 * E_DIM + col]       = make_float2(acc[mi][ni][0], acc[mi][ni][1]);
            *(float2*)&Cg[(r0 + 8) * E_DIM + col] = make_float2(acc[mi][ni][2], acc[mi][ni][3]);
        }
    }
}

// ===========================================================================
// RoPE (in-place on q and k slices of g_qkv)
// ===========================================================================
__global__ void rope_kernel(float* __restrict__ qkv,
                            const float* __restrict__ cosv,
                            const float* __restrict__ sinv)
{
    long long idx = (long long)blockIdx.x * blockDim.x + threadIdx.x;
    if (idx >= 2LL * T_TOK * H_NUM * 64) return;
    int j = idx & 63;
    int h = (idx >> 6) & (H_NUM - 1);
    long long t = (idx >> 11) & (T_TOK - 1);
    int which = (int)(idx >> 23);   // 0 = q, 1 = k
    float* base = qkv + (long long)which * T_TOK * E_DIM + t * E_DIM + h * D_HEAD;
    float c = cosv[t * 64 + j];
    float s = sinv[t * 64 + j];
    float x1 = base[j];
    float x2 = base[j + 64];
    base[j]      = x1 * c - x2 * s;
    base[j + 64] = x2 * c + x1 * s;
}

// ===========================================================================
// KV cache scatter
// ===========================================================================
__global__ void cache_write_kernel(const float* __restrict__ qkv,
                                   const int* __restrict__ block_tables,
                                   float* __restrict__ out_k,
                                   float* __restrict__ out_v)
{
    long long idx = (long long)blockIdx.x * blockDim.x + threadIdx.x;
    if (idx >= (long long)B_SZ * NB_BLK * H_NUM * BS_BLK * D_HEAD) return;
    int d  = idx & 127;
    int bs = (idx >> 7) & (BS_BLK - 1);
    int h  = (idx >> 11) & (H_NUM - 1);
    long long nbb = idx >> 16;
    int b  = (int)(nbb >> 6);
    int nb = (int)(nbb & 63);
    int blk = block_tables[b * NB_BLK + nb];
    long long t = (long long)b * S_LEN + nb * BS_BLK + bs;
    long long src = t * E_DIM + h * D_HEAD + d;
    long long dst = (((long long)blk * H_NUM + h) * BS_BLK + bs) * D_HEAD + d;
    out_k[dst] = qkv[(long long)T_TOK * E_DIM + src];
    out_v[dst] = qkv[2LL * T_TOK * E_DIM + src];
}

// ===========================================================================
// Flash attention, fp32, causal. Writes hi/lo half planes for the O-proj GEMM.
// ===========================================================================
#define QS_STRIDE 129
#define KS_STRIDE 129
#define VS_STRIDE 132
#define PS_STRIDE 65

__global__ __launch_bounds__(256, 1)
void attn_kernel(const float* __restrict__ qkv,
                 __half* __restrict__ ohi, __half* __restrict__ olo)
{
    extern __shared__ float smf[];
    float* Qs = smf;
    float* Ks = Qs + 64 * QS_STRIDE;
    float* Vs = Ks + 64 * KS_STRIDE;
    float* Ps = Vs + 64 * VS_STRIDE;
    float* alpha_sh = Ps + 64 * PS_STRIDE;
    float* l_sh = alpha_sh + 64;

    int tid = threadIdx.x;
    int tx = tid & 15, ty = tid >> 4;
    int qt = blockIdx.x, h = blockIdx.y, b = blockIdx.z;
    int q0 = qt * 64;

    const long long TE = (long long)T_TOK * E_DIM;
    const float* qbase = qkv;
    const float* kbase = qkv + TE;
    const float* vbase = qkv + 2 * TE;
    const float scale = 0.08838834764831845f;

    for (int c = tid; c < 64 * 32; c += 256) {
        int row = c >> 5;
        int c4 = (c & 31) * 4;
        float4 v = *(const float4*)&qbase[((long long)(b * S_LEN + q0 + row)) * E_DIM + h * D_HEAD + c4];
        Qs[row * QS_STRIDE + c4]     = v.x;
        Qs[row * QS_STRIDE + c4 + 1] = v.y;
        Qs[row * QS_STRIDE + c4 + 2] = v.z;
        Qs[row * QS_STRIDE + c4 + 3] = v.w;
    }

    float m_r = -1e30f, l_r = 0.f;
    float o[4][8];
    #pragma unroll
    for (int i = 0; i < 4; i++)
        #pragma unroll
        for (int j = 0; j < 8; j++) o[i][j] = 0.f;

    int nkt = qt + 1;
    for (int kt = 0; kt < nkt; kt++) {
        int k0 = kt * 64;
        __syncthreads();
        for (int c = tid; c < 64 * 32; c += 256) {
            int row = c >> 5;
            int c4 = (c & 31) * 4;
            long long goff = ((long long)(b * S_LEN + k0 + row)) * E_DIM + h * D_HEAD + c4;
            float4 kv = *(const float4*)&kbase[goff];
            Ks[row * KS_STRIDE + c4]     = kv.x;
            Ks[row * KS_STRIDE + c4 + 1] = kv.y;
            Ks[row * KS_STRIDE + c4 + 2] = kv.z;
            Ks[row * KS_STRIDE + c4 + 3] = kv.w;
            float4 vv = *(const float4*)&vbase[goff];
            *(float4*)&Vs[row * VS_STRIDE + c4] = vv;
        }
        __syncthreads();

        float s[4][4];
        #pragma unroll
        for (int i = 0; i < 4; i++)
            #pragma unroll
            for (int j = 0; j < 4; j++) s[i][j] = 0.f;
        const float* qr0 = &Qs[(ty +  0) * QS_STRIDE];
        const float* qr1 = &Qs[(ty + 16) * QS_STRIDE];
        const float* qr2 = &Qs[(ty + 32) * QS_STRIDE];
        const float* qr3 = &Qs[(ty + 48) * QS_STRIDE];
        const float* kr0 = &Ks[(tx +  0) * KS_STRIDE];
        const float* kr1 = &Ks[(tx + 16) * KS_STRIDE];
        const float* kr2 = &Ks[(tx + 32) * KS_STRIDE];
        const float* kr3 = &Ks[(tx + 48) * KS_STRIDE];
        #pragma unroll 4
        for (int d = 0; d < 128; d++) {
            float a0 = qr0[d], a1 = qr1[d], a2 = qr2[d], a3 = qr3[d];
            float b0 = kr0[d], b1 = kr1[d], b2 = kr2[d], b3 = kr3[d];
            s[0][0] += a0 * b0; s[0][1] += a0 * b1; s[0][2] += a0 * b2; s[0][3] += a0 * b3;
            s[1][0] += a1 * b0; s[1][1] += a1 * b1; s[1][2] += a1 * b2; s[1][3] += a1 * b3;
            s[2][0] += a2 * b0; s[2][1] += a2 * b1; s[2][2] += a2 * b2; s[2][3] += a2 * b3;
            s[3][0] += a3 * b0; s[3][1] += a3 * b1; s[3][2] += a3 * b2; s[3][3] += a3 * b3;
        }
        bool diag = (kt == qt);
        #pragma unroll
        for (int i = 0; i < 4; i++) {
            int qi = ty + 16 * i;
            #pragma unroll
            for (int j = 0; j < 4; j++) {
                int ki = tx + 16 * j;
                float val = s[i][j] * scale;
                if (diag && ki > qi) val = -1e30f;
                Ps[qi * PS_STRIDE + ki] = val;
            }
        }
        __syncthreads();

        {
            int q = tid >> 2;
            int cc = (tid & 3) * 16;
            float* pr = &Ps[q * PS_STRIDE + cc];
            float mx = -1e30f;
            #pragma unroll
            for (int c = 0; c < 16; c++) mx = fmaxf(mx, pr[c]);
            mx = fmaxf(mx, __shfl_xor_sync(0xffffffffu, mx, 1));
            mx = fmaxf(mx, __shfl_xor_sync(0xffffffffu, mx, 2));
            float m_new = fmaxf(m_r, mx);
            float al = __expf(m_r - m_new);
            float sum = 0.f;
            #pragma unroll
            for (int c = 0; c < 16; c++) {
                float p = __expf(pr[c] - m_new);
                pr[c] = p;
                sum += p;
            }
            sum += __shfl_xor_sync(0xffffffffu, sum, 1);
            sum += __shfl_xor_sync(0xffffffffu, sum, 2);
            l_r = l_r * al + sum;
            m_r = m_new;
            if ((tid & 3) == 0) { alpha_sh[q] = al; l_sh[q] = l_r; }
        }
        __syncthreads();

        float av[4];
        #pragma unroll
        for (int i = 0; i < 4; i++) av[i] = alpha_sh[ty + 16 * i];
        #pragma unroll
        for (int i = 0; i < 4; i++)
            #pragma unroll
            for (int j = 0; j < 8; j++) o[i][j] *= av[i];

        #pragma unroll 2
        for (int k = 0; k < 64; k++) {
            float p0 = Ps[(ty +  0) * PS_STRIDE + k];
            float p1 = Ps[(ty + 16) * PS_STRIDE + k];
            float p2 = Ps[(ty + 32) * PS_STRIDE + k];
            float p3 = Ps[(ty + 48) * PS_STRIDE + k];
            float4 v0 = *(float4*)&Vs[k * VS_STRIDE + tx * 8];
            float4 v1 = *(float4*)&Vs[k * VS_STRIDE + tx * 8 + 4];
            o[0][0] += p0 * v0.x; o[0][1] += p0 * v0.y; o[0][2] += p0 * v0.z; o[0][3] += p0 * v0.w;
            o[0][4] += p0 * v1.x; o[0][5] += p0 * v1.y; o[0][6] += p0 * v1.z; o[0][7] += p0 * v1.w;
            o[1][0] += p1 * v0.x; o[1][1] += p1 * v0.y; o[1][2] += p1 * v0.z; o[1][3] += p1 * v0.w;
            o[1][4] += p1 * v1.x; o[1][5] += p1 * v1.y; o[1][6] += p1 * v1.z; o[1][7] += p1 * v1.w;
            o[2][0] += p2 * v0.x; o[2][1] += p2 * v0.y; o[2][2] += p2 * v0.z; o[2][3] += p2 * v0.w;
            o[2][4] += p2 * v1.x; o[2][5] += p2 * v1.y; o[2][6] += p2 * v1.z; o[2][7] += p2 * v1.w;
            o[3][0] += p3 * v0.x; o[3][1] += p3 * v0.y; o[3][2] += p3 * v0.z; o[3][3] += p3 * v0.w;
            o[3][4] += p3 * v1.x; o[3][5] += p3 * v1.y; o[3][6] += p3 * v1.z; o[3][7] += p3 * v1.w;
        }
    }

    #pragma unroll
    for (int i = 0; i < 4; i++) {
        int qi = ty + 16 * i;
        float inv = 1.f / l_sh[qi];
        long long off = ((long long)(b * S_LEN + q0 + qi)) * E_DIM + h * D_HEAD + tx * 8;
        #pragma unroll
        for (int jp = 0; jp < 4; jp++) {
            float v0 = o[i][jp * 2] * inv;
            float v1 = o[i][jp * 2 + 1] * inv;
            __half h0 = __float2half_rn(v0), h1 = __float2half_rn(v1);
            __half l0 = __float2half_rn(v0 - __half2float(h0));
            __half l1 = __float2half_rn(v1 - __half2float(h1));
            *(half2*)&ohi[off + jp * 2] = __halves2half2(h0, h1);
            *(half2*)&olo[off + jp * 2] = __halves2half2(l0, l1);
        }
    }
}

// ===========================================================================
extern "C" void kernel_launch(void* const* d_in, const int* in_sizes, int n_in,
                              void* d_out, int out_size)
{
    const float* hidden   = (const float*)d_in[0];
    const float* qkv_w    = (const float*)d_in[1];
    const float* o_w      = (const float*)d_in[2];
    const float* cosv     = (const float*)d_in[3];
    const float* sinv     = (const float*)d_in[4];
    const int*   blk_tab  = (const int*)d_in[7];

    float* out   = (float*)d_out;
    float* out_k = out + (size_t)T_TOK * E_DIM;
    float* out_v = out_k + (size_t)T_TOK * E_DIM;

    float*  qkv;  cudaGetSymbolAddress((void**)&qkv,  g_qkv);
    __half* wth;  cudaGetSymbolAddress((void**)&wth,  g_wt_hi);
    __half* wtl;  cudaGetSymbolAddress((void**)&wtl,  g_wt_lo);
    __half* ahi;  cudaGetSymbolAddress((void**)&ahi,  g_ahi);
    __half* alo;  cudaGetSymbolAddress((void**)&alo,  g_alo);

    // 0a) Transpose + split weights
    transpose_split_kernel<<<dim3(E_DIM / 32, E_DIM / 32, 4), dim3(32, 8)>>>(qkv_w, o_w, wth, wtl);
    // 0b) Split hidden activations
    {
        long long total = (long long)T_TOK * E_DIM / 4;
        split_a_kernel<<<(unsigned)((total + 255) / 256), 256>>>(hidden, ahi, alo);
    }

    // 1) QKV projection (fp16 split mma + ldmatrix, occ 2)
    cudaFuncSetAttribute(gemm_mma_kernel, cudaFuncAttributeMaxDynamicSharedMemorySize, GEMM_SMEM);
    gemm_mma_kernel<<<dim3(E_DIM / 128, T_TOK / 128, 3), 256, GEMM_SMEM>>>(
        ahi, alo, wth, wtl, qkv, (long long)E_DIM * E_DIM, (long long)T_TOK * E_DIM);

    // 2) RoPE on q and k
    {
        long long total = 2LL * T_TOK * H_NUM * 64;
        rope_kernel<<<(unsigned)((total + 255) / 256), 256>>>(qkv, cosv, sinv);
    }

    // 3) KV cache scatter
    {
        long long total = (long long)B_SZ * NB_BLK * H_NUM * BS_BLK * D_HEAD;
        cache_write_kernel<<<(unsigned)((total + 255) / 256), 256>>>(qkv, blk_tab, out_k, out_v);
    }

    // 4) Flash attention (fp32 compute, hi/lo half output)
    {
        int smem = (64 * QS_STRIDE + 64 * KS_STRIDE + 64 * VS_STRIDE +
                    64 * PS_STRIDE + 64 + 64) * (int)sizeof(float);
        cudaFuncSetAttribute(attn_kernel, cudaFuncAttributeMaxDynamicSharedMemorySize, smem);
        attn_kernel<<<dim3(S_LEN / 64, H_NUM, B_SZ), 256, smem>>>(qkv, ahi, alo);
    }

    // 5) Output projection (fp16 split mma + ldmatrix, occ 2)
    gemm_mma_kernel<<<dim3(E_DIM / 128, T_TOK / 128, 1), 256, GEMM_SMEM>>>(
        ahi, alo, wth + 3ULL * E_DIM * E_DIM, wtl + 3ULL * E_DIM * E_DIM, out, 0, 0);
}

// round 13
// speedup vs baseline: 2.4016x; 1.0289x over previous
#include <cuda_runtime.h>
#include <cuda_fp16.h>
#include <cstdint>

#define T_TOK 4096
#define E_DIM 4096
#define B_SZ  4
#define S_LEN 1024
#define H_NUM 32
#define D_HEAD 128
#define BS_BLK 16
#define NB_BLK 64

// Scratch (allocation-free rule: __device__ globals)
__device__ float  g_qkv[3ULL * T_TOK * E_DIM];        // q | k | v, each [T, E] fp32
__device__ __half g_wt_hi[4ULL * E_DIM * E_DIM];      // transposed weight hi planes [4][N][K]
__device__ __half g_wt_lo[4ULL * E_DIM * E_DIM];      // transposed weight lo planes
__device__ __half g_ahi[(size_t)T_TOK * E_DIM];       // activation hi plane [T, E]
__device__ __half g_alo[(size_t)T_TOK * E_DIM];       // activation lo plane

// ===========================================================================
// helpers
// ===========================================================================
__device__ __forceinline__ uint32_t smem_u32(const void* p) {
    uint32_t a;
    asm("{ .reg .u64 t; cvta.to.shared.u64 t, %1; cvt.u32.u64 %0, t; }" : "=r"(a) : "l"(p));
    return a;
}
__device__ __forceinline__ void cp16(uint32_t dst, const void* src) {
    asm volatile("cp.async.ca.shared.global [%0], [%1], 16;" :: "r"(dst), "l"(src));
}
#define CP_COMMIT() asm volatile("cp.async.commit_group;" ::: "memory")
#define CP_WAIT0()  asm volatile("cp.async.wait_group 0;" ::: "memory")

__device__ __forceinline__ void mma_f16(float* c, const uint32_t* a, const uint32_t* b) {
    asm volatile(
        "mma.sync.aligned.m16n8k16.row.col.f32.f16.f16.f32 "
        "{%0,%1,%2,%3}, {%4,%5,%6,%7}, {%8,%9}, {%0,%1,%2,%3};"
        : "+f"(c[0]), "+f"(c[1]), "+f"(c[2]), "+f"(c[3])
        : "r"(a[0]), "r"(a[1]), "r"(a[2]), "r"(a[3]), "r"(b[0]), "r"(b[1]));
}
__device__ __forceinline__ void ldmatrix_x4(uint32_t* r, uint32_t addr) {
    asm volatile("ldmatrix.sync.aligned.m8n8.x4.shared.b16 {%0,%1,%2,%3}, [%4];"
                 : "=r"(r[0]), "=r"(r[1]), "=r"(r[2]), "=r"(r[3]) : "r"(addr));
}

// Packed fp32x2 ops (Blackwell)
#define FMA2(acc, a, b) \
    asm("fma.rn.f32x2 %0, %1, %2, %0;" : "+l"(acc) : "l"(a), "l"(b))
#define MUL2(out, a, b) \
    asm("mul.rn.f32x2 %0, %1, %2;" : "=l"(out) : "l"(a), "l"(b))
#define PACK2(out, lo, hi) \
    asm("mov.b64 %0, {%1, %2};" : "=l"(out) : "f"(lo), "f"(hi))
#define UNPACK2(lo, hi, in) \
    asm("mov.b64 {%0, %1}, %2;" : "=f"(lo), "=f"(hi) : "l"(in))

// ===========================================================================
// Weight transpose + hi/lo split: W[z][k][n] fp32 -> Wt_hi/lo[z][n][k] half
// ===========================================================================
__global__ void transpose_split_kernel(const float* __restrict__ qkv_w,
                                       const float* __restrict__ o_w,
                                       __half* __restrict__ out_hi,
                                       __half* __restrict__ out_lo)
{
    __shared__ float tile[32][33];
    int z = blockIdx.z;
    const float* src = (z < 3) ? qkv_w + (size_t)z * E_DIM * E_DIM : o_w;
    __half* dhi = out_hi + (size_t)z * E_DIM * E_DIM;
    __half* dlo = out_lo + (size_t)z * E_DIM * E_DIM;
    int k0 = blockIdx.y * 32, n0 = blockIdx.x * 32;
    int tx = threadIdx.x, ty = threadIdx.y;
    #pragma unroll
    for (int j = 0; j < 32; j += 8)
        tile[ty + j][tx] = src[(size_t)(k0 + ty + j) * E_DIM + n0 + tx];
    __syncthreads();
    #pragma unroll
    for (int j = 0; j < 32; j += 8) {
        float x = tile[tx][ty + j];
        __half hi = __float2half_rn(x);
        __half lo = __float2half_rn(x - __half2float(hi));
        size_t off = (size_t)(n0 + ty + j) * E_DIM + k0 + tx;
        dhi[off] = hi;
        dlo[off] = lo;
    }
}

// ===========================================================================
// Activation hi/lo split: X[T,E] fp32 -> hi/lo half planes
// ===========================================================================
__global__ void split_a_kernel(const float* __restrict__ x,
                               __half* __restrict__ xhi, __half* __restrict__ xlo)
{
    long long i = ((long long)blockIdx.x * blockDim.x + threadIdx.x) * 4;
    if (i >= (long long)T_TOK * E_DIM) return;
    float4 v = *(const float4*)&x[i];
    __half h0 = __float2half_rn(v.x), h1 = __float2half_rn(v.y);
    __half h2 = __float2half_rn(v.z), h3 = __float2half_rn(v.w);
    __half l0 = __float2half_rn(v.x - __half2float(h0));
    __half l1 = __float2half_rn(v.y - __half2float(h1));
    __half l2 = __float2half_rn(v.z - __half2float(h2));
    __half l3 = __float2half_rn(v.w - __half2float(h3));
    *(half2*)&xhi[i]     = __halves2half2(h0, h1);
    *(half2*)&xhi[i + 2] = __halves2half2(h2, h3);
    *(half2*)&xlo[i]     = __halves2half2(l0, l1);
    *(half2*)&xlo[i + 2] = __halves2half2(l2, l3);
}

// ===========================================================================
// fp16 hi/lo split GEMM with ldmatrix (unchanged from R12 — at legacy-pipe cap)
// ===========================================================================
#define KT 16
#define NK_ITERS (E_DIM / KT)              // 256
#define ROW_B 80                           // bytes per row
#define TILE_B (128 * ROW_B)               // 10240 per matrix per stage
#define STAGE_B (2 * TILE_B)               // 20480
#define NSTAGES 2
#define GEMM_SMEM (NSTAGES * STAGE_B)      // 40960

__device__ __forceinline__ void stage_load(uint32_t smb, int st,
                                           const __half* __restrict__ Ahi,
                                           const __half* __restrict__ Alo,
                                           const __half* __restrict__ Bhi,
                                           const __half* __restrict__ Blo,
                                           int k0, int tid)
{
    #pragma unroll
    for (int j = 0; j < 4; ++j) {
        int idx = tid + 256 * j;
        int m   = idx >> 9;
        int r   = (idx >> 2) & 127;
        int seg = idx & 3;                 // 0,1 = hi halves ; 2,3 = lo halves
        uint32_t dst = smb + st * STAGE_B + m * TILE_B + r * ROW_B + seg * 16;
        const __half* hp = m ? Bhi : Ahi;
        const __half* lp = m ? Blo : Alo;
        const __half* src = (seg < 2 ? hp : lp) + (long long)r * E_DIM + k0 + (seg & 1) * 8;
        cp16(dst, src);
    }
}

__global__ __launch_bounds__(256, 2)
void gemm_mma_kernel(const __half* __restrict__ Ahi, const __half* __restrict__ Alo,
                     const __half* __restrict__ Bhi, const __half* __restrict__ Blo,
                     float* __restrict__ C, long long strideB, long long strideC)
{
    extern __shared__ char sm[];
    uint32_t smb = smem_u32(sm);
    const int tid = threadIdx.x;
    const int wid = tid >> 5;
    const int lane = tid & 31;
    const int grp = lane >> 2;
    const int thr = lane & 3;
    const int warp_m = wid >> 2;
    const int warp_n = wid & 3;

    const int m0 = blockIdx.y * 128;
    const int n0 = blockIdx.x * 128;
    const __half* Ah = Ahi + (long long)m0 * E_DIM;
    const __half* Al = Alo + (long long)m0 * E_DIM;
    const __half* Bh = Bhi + (long long)blockIdx.z * strideB + (long long)n0 * E_DIM;
    const __half* Bl = Blo + (long long)blockIdx.z * strideB + (long long)n0 * E_DIM;
    float* Cg = C + (long long)blockIdx.z * strideC;

    float acc[4][4][4];
    #pragma unroll
    for (int mi = 0; mi < 4; mi++)
        #pragma unroll
        for (int ni = 0; ni < 4; ni++)
            #pragma unroll
            for (int q = 0; q < 4; q++) acc[mi][ni][q] = 0.f;

    const uint32_t a_lane_off =
        (uint32_t)((warp_m * 64 + (lane & 15)) * ROW_B + (lane >> 4) * 16);
    const uint32_t b_lane_off =
        (uint32_t)((warp_n * 32 + (lane >> 4) * 8 + (lane & 7)) * ROW_B + ((lane >> 3) & 1) * 16);

    stage_load(smb, 0, Ah, Al, Bh, Bl, 0, tid);
    CP_COMMIT();

    for (int kt = 0; kt < NK_ITERS; ++kt) {
        int st = kt & 1;
        CP_WAIT0();
        __syncthreads();

        if (kt + 1 < NK_ITERS) {
            stage_load(smb, (kt + 1) & 1, Ah, Al, Bh, Bl, (kt + 1) * KT, tid);
            CP_COMMIT();
        }

        uint32_t abase = smb + st * STAGE_B + a_lane_off;
        uint32_t bbase = smb + st * STAGE_B + TILE_B + b_lane_off;

        uint32_t ah[4][4], al[4][4];
        #pragma unroll
        for (int mi = 0; mi < 4; mi++) {
            ldmatrix_x4(ah[mi], abase + mi * 16 * ROW_B);
            ldmatrix_x4(al[mi], abase + mi * 16 * ROW_B + 32);
        }
        #pragma unroll
        for (int g = 0; g < 2; g++) {
            uint32_t bh[4], bl[4];
            ldmatrix_x4(bh, bbase + g * 16 * ROW_B);
            ldmatrix_x4(bl, bbase + g * 16 * ROW_B + 32);
            #pragma unroll
            for (int mi = 0; mi < 4; mi++)
                #pragma unroll
                for (int nj = 0; nj < 2; nj++) {
                    float* accp = acc[mi][g * 2 + nj];
                    mma_f16(accp, al[mi], &bh[nj * 2]);
                    mma_f16(accp, ah[mi], &bl[nj * 2]);
                    mma_f16(accp, ah[mi], &bh[nj * 2]);
                }
        }
    }

    #pragma unroll
    for (int mi = 0; mi < 4; mi++) {
        long long r0 = m0 + warp_m * 64 + mi * 16 + grp;
        #pragma unroll
        for (int ni = 0; ni < 4; ni++) {
            long long col = n0 + warp_n * 32 + ni * 8 + thr * 2;
            *(float2*)&Cg[r0 * E_DIM + col]       = make_float2(acc[mi][ni][0], acc[mi][ni][1]);
            *(float2*)&Cg[(r0 + 8) * E_DIM + col] = make_float2(acc[mi][ni][2], acc[mi][ni][3]);
        }
    }
}

// ===========================================================================
// RoPE (in-place on q and k slices of g_qkv)
// ===========================================================================
__global__ void rope_kernel(float* __restrict__ qkv,
                            const float* __restrict__ cosv,
                            const float* __restrict__ sinv)
{
    long long idx = (long long)blockIdx.x * blockDim.x + threadIdx.x;
    if (idx >= 2LL * T_TOK * H_NUM * 64) return;
    int j = idx & 63;
    int h = (idx >> 6) & (H_NUM - 1);
    long long t = (idx >> 11) & (T_TOK - 1);
    int which = (int)(idx >> 23);   // 0 = q, 1 = k
    float* base = qkv + (long long)which * T_TOK * E_DIM + t * E_DIM + h * D_HEAD;
    float c = cosv[t * 64 + j];
    float s = sinv[t * 64 + j];
    float x1 = base[j];
    float x2 = base[j + 64];
    base[j]      = x1 * c - x2 * s;
    base[j + 64] = x2 * c + x1 * s;
}

// ===========================================================================
// KV cache scatter
// ===========================================================================
__global__ void cache_write_kernel(const float* __restrict__ qkv,
                                   const int* __restrict__ block_tables,
                                   float* __restrict__ out_k,
                                   float* __restrict__ out_v)
{
    long long idx = (long long)blockIdx.x * blockDim.x + threadIdx.x;
    if (idx >= (long long)B_SZ * NB_BLK * H_NUM * BS_BLK * D_HEAD) return;
    int d  = idx & 127;
    int bs = (idx >> 7) & (BS_BLK - 1);
    int h  = (idx >> 11) & (H_NUM - 1);
    long long nbb = idx >> 16;
    int b  = (int)(nbb >> 6);
    int nb = (int)(nbb & 63);
    int blk = block_tables[b * NB_BLK + nb];
    long long t = (long long)b * S_LEN + nb * BS_BLK + bs;
    long long src = t * E_DIM + h * D_HEAD + d;
    long long dst = (((long long)blk * H_NUM + h) * BS_BLK + bs) * D_HEAD + d;
    out_k[dst] = qkv[(long long)T_TOK * E_DIM + src];
    out_v[dst] = qkv[2LL * T_TOK * E_DIM + src];
}

// ===========================================================================
// Flash attention, fp32 with packed f32x2 FMA, causal.
// Writes hi/lo half planes for the O-proj GEMM.
// Q/K smem stride 130 (even -> 8B-aligned LDS.64; 130 % 32 == 2 -> 16 distinct
// even-bank starts for the 16 K-rows per warp).
// ===========================================================================
#define QS_STRIDE 130
#define KS_STRIDE 130
#define VS_STRIDE 132
#define PS_STRIDE 65

__global__ __launch_bounds__(256, 1)
void attn_kernel(const float* __restrict__ qkv,
                 __half* __restrict__ ohi, __half* __restrict__ olo)
{
    extern __shared__ float smf[];
    float* Qs = smf;
    float* Ks = Qs + 64 * QS_STRIDE;
    float* Vs = Ks + 64 * KS_STRIDE;
    float* Ps = Vs + 64 * VS_STRIDE;
    float* alpha_sh = Ps + 64 * PS_STRIDE;
    float* l_sh = alpha_sh + 64;

    int tid = threadIdx.x;
    int tx = tid & 15, ty = tid >> 4;
    int qt = blockIdx.x, h = blockIdx.y, b = blockIdx.z;
    int q0 = qt * 64;

    const long long TE = (long long)T_TOK * E_DIM;
    const float* qbase = qkv;
    const float* kbase = qkv + TE;
    const float* vbase = qkv + 2 * TE;
    const float scale = 0.08838834764831845f;

    // Load Q tile (float2 stores: stride 130 keeps 8B alignment on every row)
    for (int c = tid; c < 64 * 32; c += 256) {
        int row = c >> 5;
        int c4 = (c & 31) * 4;
        float4 v = *(const float4*)&qbase[((long long)(b * S_LEN + q0 + row)) * E_DIM + h * D_HEAD + c4];
        *(float2*)&Qs[row * QS_STRIDE + c4]     = make_float2(v.x, v.y);
        *(float2*)&Qs[row * QS_STRIDE + c4 + 2] = make_float2(v.z, v.w);
    }

    float m_r = -1e30f, l_r = 0.f;
    uint64_t o2[4][4];     // packed (even-d, odd-d) accumulators
    #pragma unroll
    for (int i = 0; i < 4; i++)
        #pragma unroll
        for (int j = 0; j < 4; j++) o2[i][j] = 0ull;

    int nkt = qt + 1;
    for (int kt = 0; kt < nkt; kt++) {
        int k0 = kt * 64;
        __syncthreads();
        for (int c = tid; c < 64 * 32; c += 256) {
            int row = c >> 5;
            int c4 = (c & 31) * 4;
            long long goff = ((long long)(b * S_LEN + k0 + row)) * E_DIM + h * D_HEAD + c4;
            float4 kv = *(const float4*)&kbase[goff];
            *(float2*)&Ks[row * KS_STRIDE + c4]     = make_float2(kv.x, kv.y);
            *(float2*)&Ks[row * KS_STRIDE + c4 + 2] = make_float2(kv.z, kv.w);
            float4 vv = *(const float4*)&vbase[goff];
            *(float4*)&Vs[row * VS_STRIDE + c4] = vv;
        }
        __syncthreads();

        // --- scores: packed partial sums over (even-d, odd-d) ---
        uint64_t s2[4][4];
        #pragma unroll
        for (int i = 0; i < 4; i++)
            #pragma unroll
            for (int j = 0; j < 4; j++) s2[i][j] = 0ull;
        const float* qr0 = &Qs[(ty +  0) * QS_STRIDE];
        const float* qr1 = &Qs[(ty + 16) * QS_STRIDE];
        const float* qr2 = &Qs[(ty + 32) * QS_STRIDE];
        const float* qr3 = &Qs[(ty + 48) * QS_STRIDE];
        const float* kr0 = &Ks[(tx +  0) * KS_STRIDE];
        const float* kr1 = &Ks[(tx + 16) * KS_STRIDE];
        const float* kr2 = &Ks[(tx + 32) * KS_STRIDE];
        const float* kr3 = &Ks[(tx + 48) * KS_STRIDE];
        #pragma unroll 4
        for (int d = 0; d < 128; d += 2) {
            uint64_t a0 = *(const uint64_t*)(qr0 + d);
            uint64_t a1 = *(const uint64_t*)(qr1 + d);
            uint64_t a2 = *(const uint64_t*)(qr2 + d);
            uint64_t a3 = *(const uint64_t*)(qr3 + d);
            uint64_t b0 = *(const uint64_t*)(kr0 + d);
            uint64_t b1 = *(const uint64_t*)(kr1 + d);
            uint64_t b2 = *(const uint64_t*)(kr2 + d);
            uint64_t b3 = *(const uint64_t*)(kr3 + d);
            FMA2(s2[0][0], a0, b0); FMA2(s2[0][1], a0, b1); FMA2(s2[0][2], a0, b2); FMA2(s2[0][3], a0, b3);
            FMA2(s2[1][0], a1, b0); FMA2(s2[1][1], a1, b1); FMA2(s2[1][2], a1, b2); FMA2(s2[1][3], a1, b3);
            FMA2(s2[2][0], a2, b0); FMA2(s2[2][1], a2, b1); FMA2(s2[2][2], a2, b2); FMA2(s2[2][3], a2, b3);
            FMA2(s2[3][0], a3, b0); FMA2(s2[3][1], a3, b1); FMA2(s2[3][2], a3, b2); FMA2(s2[3][3], a3, b3);
        }
        bool diag = (kt == qt);
        #pragma unroll
        for (int i = 0; i < 4; i++) {
            int qi = ty + 16 * i;
            #pragma unroll
            for (int j = 0; j < 4; j++) {
                int ki = tx + 16 * j;
                float lo, hi;
                UNPACK2(lo, hi, s2[i][j]);
                float val = (lo + hi) * scale;
                if (diag && ki > qi) val = -1e30f;
                Ps[qi * PS_STRIDE + ki] = val;
            }
        }
        __syncthreads();

        // --- online softmax: row q = tid/4, 16 cols per thread ---
        {
            int q = tid >> 2;
            int cc = (tid & 3) * 16;
            float* pr = &Ps[q * PS_STRIDE + cc];
            float mx = -1e30f;
            #pragma unroll
            for (int c = 0; c < 16; c++) mx = fmaxf(mx, pr[c]);
            mx = fmaxf(mx, __shfl_xor_sync(0xffffffffu, mx, 1));
            mx = fmaxf(mx, __shfl_xor_sync(0xffffffffu, mx, 2));
            float m_new = fmaxf(m_r, mx);
            float al = __expf(m_r - m_new);
            float sum = 0.f;
            #pragma unroll
            for (int c = 0; c < 16; c++) {
                float p = __expf(pr[c] - m_new);
                pr[c] = p;
                sum += p;
            }
            sum += __shfl_xor_sync(0xffffffffu, sum, 1);
            sum += __shfl_xor_sync(0xffffffffu, sum, 2);
            l_r = l_r * al + sum;
            m_r = m_new;
            if ((tid & 3) == 0) { alpha_sh[q] = al; l_sh[q] = l_r; }
        }
        __syncthreads();

        // --- rescale + PV accumulate (packed) ---
        #pragma unroll
        for (int i = 0; i < 4; i++) {
            float av = alpha_sh[ty + 16 * i];
            uint64_t avp; PACK2(avp, av, av);
            #pragma unroll
            for (int j = 0; j < 4; j++) { uint64_t t; MUL2(t, o2[i][j], avp); o2[i][j] = t; }
        }

        #pragma unroll 2
        for (int k = 0; k < 64; k++) {
            float p0 = Ps[(ty +  0) * PS_STRIDE + k];
            float p1 = Ps[(ty + 16) * PS_STRIDE + k];
            float p2 = Ps[(ty + 32) * PS_STRIDE + k];
            float p3 = Ps[(ty + 48) * PS_STRIDE + k];
            uint64_t pp0, pp1, pp2, pp3;
            PACK2(pp0, p0, p0); PACK2(pp1, p1, p1);
            PACK2(pp2, p2, p2); PACK2(pp3, p3, p3);
            float4 v0 = *(float4*)&Vs[k * VS_STRIDE + tx * 8];
            float4 v1 = *(float4*)&Vs[k * VS_STRIDE + tx * 8 + 4];
            uint64_t vv0, vv1, vv2, vv3;
            PACK2(vv0, v0.x, v0.y); PACK2(vv1, v0.z, v0.w);
            PACK2(vv2, v1.x, v1.y); PACK2(vv3, v1.z, v1.w);
            FMA2(o2[0][0], pp0, vv0); FMA2(o2[0][1], pp0, vv1); FMA2(o2[0][2], pp0, vv2); FMA2(o2[0][3], pp0, vv3);
            FMA2(o2[1][0], pp1, vv0); FMA2(o2[1][1], pp1, vv1); FMA2(o2[1][2], pp1, vv2); FMA2(o2[1][3], pp1, vv3);
            FMA2(o2[2][0], pp2, vv0); FMA2(o2[2][1], pp2, vv1); FMA2(o2[2][2], pp2, vv2); FMA2(o2[2][3], pp2, vv3);
            FMA2(o2[3][0], pp3, vv0); FMA2(o2[3][1], pp3, vv1); FMA2(o2[3][2], pp3, vv2); FMA2(o2[3][3], pp3, vv3);
        }
    }

    // normalize + store as hi/lo half planes
    #pragma unroll
    for (int i = 0; i < 4; i++) {
        int qi = ty + 16 * i;
        float inv = 1.f / l_sh[qi];
        long long off = ((long long)(b * S_LEN + q0 + qi)) * E_DIM + h * D_HEAD + tx * 8;
        #pragma unroll
        for (int jp = 0; jp < 4; jp++) {
            float e0, e1;
            UNPACK2(e0, e1, o2[i][jp]);
            float v0 = e0 * inv;
            float v1 = e1 * inv;
            __half h0 = __float2half_rn(v0), h1 = __float2half_rn(v1);
            __half l0 = __float2half_rn(v0 - __half2float(h0));
            __half l1 = __float2half_rn(v1 - __half2float(h1));
            *(half2*)&ohi[off + jp * 2] = __halves2half2(h0, h1);
            *(half2*)&olo[off + jp * 2] = __halves2half2(l0, l1);
        }
    }
}

// ===========================================================================
extern "C" void kernel_launch(void* const* d_in, const int* in_sizes, int n_in,
                              void* d_out, int out_size)
{
    const float* hidden   = (const float*)d_in[0];
    const float* qkv_w    = (const float*)d_in[1];
    const float* o_w      = (const float*)d_in[2];
    const float* cosv     = (const float*)d_in[3];
    const float* sinv     = (const float*)d_in[4];
    const int*   blk_tab  = (const int*)d_in[7];

    float* out   = (float*)d_out;
    float* out_k = out + (size_t)T_TOK * E_DIM;
    float* out_v = out_k + (size_t)T_TOK * E_DIM;

    float*  qkv;  cudaGetSymbolAddress((void**)&qkv,  g_qkv);
    __half* wth;  cudaGetSymbolAddress((void**)&wth,  g_wt_hi);
    __half* wtl;  cudaGetSymbolAddress((void**)&wtl,  g_wt_lo);
    __half* ahi;  cudaGetSymbolAddress((void**)&ahi,  g_ahi);
    __half* alo;  cudaGetSymbolAddress((void**)&alo,  g_alo);

    // 0a) Transpose + split weights
    transpose_split_kernel<<<dim3(E_DIM / 32, E_DIM / 32, 4), dim3(32, 8)>>>(qkv_w, o_w, wth, wtl);
    // 0b) Split hidden activations
    {
        long long total = (long long)T_TOK * E_DIM / 4;
        split_a_kernel<<<(unsigned)((total + 255) / 256), 256>>>(hidden, ahi, alo);
    }

    // 1) QKV projection (fp16 split mma + ldmatrix, occ 2)
    cudaFuncSetAttribute(gemm_mma_kernel, cudaFuncAttributeMaxDynamicSharedMemorySize, GEMM_SMEM);
    gemm_mma_kernel<<<dim3(E_DIM / 128, T_TOK / 128, 3), 256, GEMM_SMEM>>>(
        ahi, alo, wth, wtl, qkv, (long long)E_DIM * E_DIM, (long long)T_TOK * E_DIM);

    // 2) RoPE on q and k
    {
        long long total = 2LL * T_TOK * H_NUM * 64;
        rope_kernel<<<(unsigned)((total + 255) / 256), 256>>>(qkv, cosv, sinv);
    }

    // 3) KV cache scatter
    {
        long long total = (long long)B_SZ * NB_BLK * H_NUM * BS_BLK * D_HEAD;
        cache_write_kernel<<<(unsigned)((total + 255) / 256), 256>>>(qkv, blk_tab, out_k, out_v);
    }

    // 4) Flash attention (packed f32x2 FMA, hi/lo half output)
    {
        int smem = (64 * QS_STRIDE + 64 * KS_STRIDE + 64 * VS_STRIDE +
                    64 * PS_STRIDE + 64 + 64) * (int)sizeof(float);
        cudaFuncSetAttribute(attn_kernel, cudaFuncAttributeMaxDynamicSharedMemorySize, smem);
        attn_kernel<<<dim3(S_LEN / 64, H_NUM, B_SZ), 256, smem>>>(qkv, ahi, alo);
    }

    // 5) Output projection (fp16 split mma + ldmatrix, occ 2)
    gemm_mma_kernel<<<dim3(E_DIM / 128, T_TOK / 128, 1), 256, GEMM_SMEM>>>(
        ahi, alo, wth + 3ULL * E_DIM * E_DIM, wtl + 3ULL * E_DIM * E_DIM, out, 0, 0);
}